// round 3
// baseline (speedup 1.0000x reference)
#include <cuda_runtime.h>
#include <math.h>

#define NN 10000
#define NE 160000
#define DI 128
#define DE 512
#define DH 256

// ---------------- scratch (device globals; no allocation allowed) ----------
__device__ __align__(16) float g_xl[NN * DE];
__device__ __align__(16) float g_xr[NN * DE];
__device__ __align__(16) float g_h[NN * DE];
__device__ __align__(16) float g_agg[NN * DE];
__device__ float g_e[NE];
__device__ float g_w[NE];
__device__ float g_nmax[NN];
__device__ float g_den[NN];
__device__ int   g_src[NE];
__device__ int   g_dst[NE];
__device__ __align__(16) float g_m1[NN * DH];
__device__ __align__(16) float g_m2[NN * DH];
__device__ float g_logit[NN];
__device__ int   g_is64;

// ---------------- edge-index dtype detection + decode -----------------------
__global__ void k_detect(const int* __restrict__ w) {
    __shared__ int s;
    if (threadIdx.x == 0) s = 0;
    __syncthreads();
    int acc = 0;
    for (int i = threadIdx.x; i < 2048; i += 256) acc |= w[2 * i + 1];
    atomicOr(&s, acc);
    __syncthreads();
    if (threadIdx.x == 0) g_is64 = (s == 0) ? 1 : 0;
}

__global__ void k_edges(const int* __restrict__ w) {
    int i = blockIdx.x * blockDim.x + threadIdx.x;
    if (i >= NE) return;
    int s, d;
    if (g_is64) { s = w[2 * i]; d = w[2 * (NE + i)]; }
    else        { s = w[i];     d = w[NE + i]; }
    if ((unsigned)s >= NN) s = 0;
    if ((unsigned)d >= NN) d = 0;
    g_src[i] = s;
    g_dst[i] = d;
}

__global__ void k_init_nodes() {
    int i = blockIdx.x * blockDim.x + threadIdx.x;
    if (i < NN) { g_nmax[i] = -3.0e38f; g_den[i] = 0.0f; }
}

__global__ void k_zero4(float4* __restrict__ p, int n4) {
    int i = blockIdx.x * blockDim.x + threadIdx.x;
    if (i < n4) p[i] = make_float4(0.f, 0.f, 0.f, 0.f);
}

// ---------------- fp32 GEMM: C[N,M] = A[N,K] @ B[K,M] ----------------------
// 128x128 block tile, 8x8 per-thread microtile, BK=16, 256 threads.
// Requires K % 16 == 0, M % 128 == 0 (K in {128,256,512}, M in {512,256}).
#define GBM 128
#define GBN 128
#define GBK 16
__global__ __launch_bounds__(256) void k_gemm(
    const float* __restrict__ A, const float* __restrict__ B,
    float* __restrict__ C, int N, int K, int M) {
    __shared__ float As[GBK][GBM];
    __shared__ float Bs[GBK][GBN];
    int tid = threadIdx.x;
    int tx = tid & 15;            // 0..15 -> col microtile
    int ty = tid >> 4;            // 0..15 -> row microtile
    int row0 = blockIdx.y * GBM;
    int col0 = blockIdx.x * GBN;

    // A-load map: 128 rows x 16 k -> 8 floats/thread (2x float4)
    int ar = tid >> 1;            // 0..127
    int ak = (tid & 1) * 8;       // 0 or 8
    // B-load map: 16 k x 128 cols -> rows bk and bk+8, float4 cols
    int bk = tid >> 5;            // 0..7
    int bc = (tid & 31) * 4;

    float acc[8][8] = {};
    float a_frag[8], b_frag[8];

    for (int k0 = 0; k0 < K; k0 += GBK) {
        float4 av0 = make_float4(0.f, 0.f, 0.f, 0.f);
        float4 av1 = av0;
        int grow = row0 + ar;
        if (grow < N) {
            const float* pA = A + (size_t)grow * K + k0 + ak;
            av0 = *(const float4*)pA;
            av1 = *(const float4*)(pA + 4);
        }
        As[ak + 0][ar] = av0.x; As[ak + 1][ar] = av0.y;
        As[ak + 2][ar] = av0.z; As[ak + 3][ar] = av0.w;
        As[ak + 4][ar] = av1.x; As[ak + 5][ar] = av1.y;
        As[ak + 6][ar] = av1.z; As[ak + 7][ar] = av1.w;

        *(float4*)&Bs[bk][bc]     = *(const float4*)(B + (size_t)(k0 + bk) * M + col0 + bc);
        *(float4*)&Bs[bk + 8][bc] = *(const float4*)(B + (size_t)(k0 + bk + 8) * M + col0 + bc);
        __syncthreads();

        #pragma unroll
        for (int kk = 0; kk < GBK; kk++) {
            *(float4*)&a_frag[0] = *(float4*)&As[kk][ty * 8];
            *(float4*)&a_frag[4] = *(float4*)&As[kk][ty * 8 + 4];
            *(float4*)&b_frag[0] = *(float4*)&Bs[kk][tx * 8];
            *(float4*)&b_frag[4] = *(float4*)&Bs[kk][tx * 8 + 4];
            #pragma unroll
            for (int i = 0; i < 8; i++)
                #pragma unroll
                for (int j = 0; j < 8; j++)
                    acc[i][j] += a_frag[i] * b_frag[j];
        }
        __syncthreads();
    }

    #pragma unroll
    for (int i = 0; i < 8; i++) {
        int r = row0 + ty * 8 + i;
        if (r < N) {
            float* pC = C + (size_t)r * M + col0 + tx * 8;
            *(float4*)pC       = *(float4*)&acc[i][0];
            *(float4*)(pC + 4) = *(float4*)&acc[i][4];
        }
    }
}

// ---------------- GATv2 edge kernels ---------------------------------------
__device__ __forceinline__ void atomicMaxF(float* addr, float val) {
    int old = __float_as_int(*addr);
    while (__int_as_float(old) < val) {
        int prev = atomicCAS((int*)addr, old, __float_as_int(val));
        if (prev == old) break;
        old = prev;
    }
}

// one warp per edge: e = att . leaky_relu(xl[src] + xr[dst], 0.2)
__global__ void k_edge_att(const float* __restrict__ att) {
    int gt = blockIdx.x * blockDim.x + threadIdx.x;
    int edge = gt >> 5;
    int lane = gt & 31;
    if (edge >= NE) return;
    int s = g_src[edge], d = g_dst[edge];
    const float4* ps = (const float4*)(g_xl + (size_t)s * DE);
    const float4* pd = (const float4*)(g_xr + (size_t)d * DE);
    const float4* pt = (const float4*)att;
    float acc = 0.f;
    #pragma unroll
    for (int i = 0; i < DE / 128; i++) {
        int k = i * 32 + lane;
        float4 a = ps[k], b = pd[k], w = pt[k];
        float v;
        v = a.x + b.x; v = (v > 0.f) ? v : 0.2f * v; acc += v * w.x;
        v = a.y + b.y; v = (v > 0.f) ? v : 0.2f * v; acc += v * w.y;
        v = a.z + b.z; v = (v > 0.f) ? v : 0.2f * v; acc += v * w.z;
        v = a.w + b.w; v = (v > 0.f) ? v : 0.2f * v; acc += v * w.w;
    }
    #pragma unroll
    for (int o = 16; o; o >>= 1) acc += __shfl_xor_sync(0xffffffffu, acc, o);
    if (lane == 0) {
        g_e[edge] = acc;
        atomicMaxF(&g_nmax[d], acc);
    }
}

// one thread per edge: w = exp(e - max[dst]); atomicAdd denom[dst]
__global__ void k_edge_w() {
    int i = blockIdx.x * blockDim.x + threadIdx.x;
    if (i >= NE) return;
    int d = g_dst[i];
    float w = expf(g_e[i] - g_nmax[d]);
    g_w[i] = w;
    atomicAdd(&g_den[d], w);
}

// one warp per edge: agg[dst] += alpha * xl[src]  (vector RED, no return)
__global__ void k_edge_agg() {
    int gt = blockIdx.x * blockDim.x + threadIdx.x;
    int edge = gt >> 5;
    int lane = gt & 31;
    if (edge >= NE) return;
    int s = g_src[edge], d = g_dst[edge];
    float alpha = g_w[edge] / (g_den[d] + 1e-16f);
    const float4* ps = (const float4*)(g_xl + (size_t)s * DE);
    float4* pa = (float4*)(g_agg + (size_t)d * DE);
    #pragma unroll
    for (int i = 0; i < DE / 128; i++) {
        int k = i * 32 + lane;
        float4 v = ps[k];
        asm volatile("red.global.add.v4.f32 [%0], {%1, %2, %3, %4};"
                     :: "l"(pa + k),
                        "f"(alpha * v.x), "f"(alpha * v.y),
                        "f"(alpha * v.z), "f"(alpha * v.w)
                     : "memory");
    }
}

// h = tanh(agg + bias)
__global__ void k_finish(const float* __restrict__ bias) {
    int i = blockIdx.x * blockDim.x + threadIdx.x;
    int n4 = NN * DE / 4;
    if (i >= n4) return;
    float4 a = ((const float4*)g_agg)[i];
    const float4* pb = (const float4*)bias;
    float4 b = pb[i & (DE / 4 - 1)];
    float4 r;
    r.x = tanhf(a.x + b.x); r.y = tanhf(a.y + b.y);
    r.z = tanhf(a.z + b.z); r.w = tanhf(a.w + b.w);
    ((float4*)g_h)[i] = r;
}

// ---------------- MLP kernels ----------------------------------------------
__global__ void k_bias_leaky(float* __restrict__ p, const float* __restrict__ c) {
    int i = blockIdx.x * blockDim.x + threadIdx.x;
    int n4 = NN * DH / 4;
    if (i >= n4) return;
    float4 v = ((const float4*)p)[i];
    float4 b = ((const float4*)c)[i & (DH / 4 - 1)];
    float4 r;
    float t;
    t = v.x + b.x; r.x = (t > 0.f) ? t : 0.1f * t;
    t = v.y + b.y; r.y = (t > 0.f) ? t : 0.1f * t;
    t = v.z + b.z; r.z = (t > 0.f) ? t : 0.1f * t;
    t = v.w + b.w; r.w = (t > 0.f) ? t : 0.1f * t;
    ((float4*)p)[i] = r;
}

// logits[n] = m2[n,:] . A3 + c3  (one warp per node)
__global__ void k_dot3(const float* __restrict__ A3, const float* __restrict__ c3) {
    int gt = blockIdx.x * blockDim.x + threadIdx.x;
    int n = gt >> 5;
    int lane = gt & 31;
    if (n >= NN) return;
    const float4* pm = (const float4*)(g_m2 + (size_t)n * DH);
    const float4* pw = (const float4*)A3;
    float acc = 0.f;
    #pragma unroll
    for (int i = 0; i < DH / 128; i++) {
        int k = i * 32 + lane;
        float4 m = pm[k], w = pw[k];
        acc += m.x * w.x + m.y * w.y + m.z * w.z + m.w * w.w;
    }
    #pragma unroll
    for (int o = 16; o; o >>= 1) acc += __shfl_xor_sync(0xffffffffu, acc, o);
    if (lane == 0) g_logit[n] = acc + c3[0];
}

// softmax over all NN logits (single block)
__global__ void k_softmax(float* __restrict__ out) {
    __shared__ float sh[1024];
    int t = threadIdx.x;
    float m = -3.0e38f;
    for (int i = t; i < NN; i += 1024) m = fmaxf(m, g_logit[i]);
    sh[t] = m; __syncthreads();
    for (int s = 512; s; s >>= 1) { if (t < s) sh[t] = fmaxf(sh[t], sh[t + s]); __syncthreads(); }
    float gm = sh[0]; __syncthreads();
    float sum = 0.f;
    for (int i = t; i < NN; i += 1024) sum += expf(g_logit[i] - gm);
    sh[t] = sum; __syncthreads();
    for (int s = 512; s; s >>= 1) { if (t < s) sh[t] += sh[t + s]; __syncthreads(); }
    float gs = sh[0];
    for (int i = t; i < NN; i += 1024) out[i] = expf(g_logit[i] - gm) / gs;
}

// ---------------- host side -------------------------------------------------
static void gat_layer(const float* hin, int din,
                      const float* Wl, const float* Wr,
                      const float* att, const float* bias,
                      float* xl, float* xr, float* agg) {
    dim3 gg(DE / GBN, (NN + GBM - 1) / GBM);
    k_gemm<<<gg, 256>>>(hin, Wl, xl, NN, din, DE);
    k_gemm<<<gg, 256>>>(hin, Wr, xr, NN, din, DE);
    k_init_nodes<<<(NN + 255) / 256, 256>>>();
    k_zero4<<<(NN * DE / 4 + 255) / 256, 256>>>((float4*)agg, NN * DE / 4);
    k_edge_att<<<(NE * 32 + 255) / 256, 256>>>(att);
    k_edge_w<<<(NE + 255) / 256, 256>>>();
    k_edge_agg<<<(NE * 32 + 255) / 256, 256>>>();
    k_finish<<<(NN * DE / 4 + 255) / 256, 256>>>(bias);
}

extern "C" void kernel_launch(void* const* d_in, const int* in_sizes, int n_in,
                              void* d_out, int out_size) {
    const float* x   = (const float*)d_in[0];
    const int*   ei  = (const int*)d_in[1];
    const float* Wl1 = (const float*)d_in[2];
    const float* Wr1 = (const float*)d_in[3];
    const float* at1 = (const float*)d_in[4];
    const float* b1  = (const float*)d_in[5];
    const float* Wl2 = (const float*)d_in[6];
    const float* Wr2 = (const float*)d_in[7];
    const float* at2 = (const float*)d_in[8];
    const float* b2  = (const float*)d_in[9];
    const float* Wl3 = (const float*)d_in[10];
    const float* Wr3 = (const float*)d_in[11];
    const float* at3 = (const float*)d_in[12];
    const float* b3  = (const float*)d_in[13];
    const float* A1  = (const float*)d_in[14];
    const float* c1  = (const float*)d_in[15];
    const float* A2  = (const float*)d_in[16];
    const float* c2  = (const float*)d_in[17];
    const float* A3  = (const float*)d_in[18];
    const float* c3  = (const float*)d_in[19];
    float* out = (float*)d_out;

    float *xl, *xr, *h, *agg, *m1, *m2;
    cudaGetSymbolAddress((void**)&xl,  g_xl);
    cudaGetSymbolAddress((void**)&xr,  g_xr);
    cudaGetSymbolAddress((void**)&h,   g_h);
    cudaGetSymbolAddress((void**)&agg, g_agg);
    cudaGetSymbolAddress((void**)&m1,  g_m1);
    cudaGetSymbolAddress((void**)&m2,  g_m2);

    k_detect<<<1, 256>>>(ei);
    k_edges<<<(NE + 255) / 256, 256>>>(ei);

    gat_layer(x, DI, Wl1, Wr1, at1, b1, xl, xr, agg);
    gat_layer(h, DE, Wl2, Wr2, at2, b2, xl, xr, agg);
    gat_layer(h, DE, Wl3, Wr3, at3, b3, xl, xr, agg);

    // MLP
    {
        dim3 g1(DH / GBN, (NN + GBM - 1) / GBM);
        dim3 g2(DE / GBN, (NN + GBM - 1) / GBM);
        k_gemm<<<g1, 256>>>(h, A1, m1, NN, DE, DH);
        k_bias_leaky<<<(NN * DH / 4 + 255) / 256, 256>>>(m1, c1);
        k_gemm<<<g1, 256>>>(m1, A2, m2, NN, DH, DH);
        k_bias_leaky<<<(NN * DH / 4 + 255) / 256, 256>>>(m2, c2);
        k_dot3<<<(NN * 32 + 255) / 256, 256>>>(A3, c3);
        k_softmax<<<1, 1024>>>(out);
    }
}

// round 5
// speedup vs baseline: 1.0945x; 1.0945x over previous
#include <cuda_runtime.h>
#include <cuda_bf16.h>
#include <math.h>
#include <stdint.h>

#define NN 10000
#define NE 160000
#define DI 128
#define DE 512
#define DH 256

// ---------------- scratch (device globals; no allocation allowed) ----------
__device__ __align__(16) float g_xl[NN * DE];
__device__ __align__(16) float g_xr[NN * DE];
__device__ __align__(16) float g_h[NN * DE];
__device__ __align__(16) float g_agg[NN * DE];
__device__ float g_e[NE];
__device__ float g_w[NE];
__device__ float g_nmax[NN];
__device__ float g_den[NN];
__device__ int   g_src[NE];
__device__ int   g_dst[NE];
__device__ __align__(16) float g_m1[NN * DH];
__device__ __align__(16) float g_m2[NN * DH];
__device__ float g_logit[NN];
__device__ int   g_is64;
// bf16 hi/lo operands (A = activations, W = weights transposed)
__device__ __align__(16) __nv_bfloat16 g_ahi[NN * DE];
__device__ __align__(16) __nv_bfloat16 g_alo[NN * DE];
__device__ __align__(16) __nv_bfloat16 g_whi[DE * DE];
__device__ __align__(16) __nv_bfloat16 g_wlo[DE * DE];

// ---------------- hi/lo split + weight transpose ----------------------------
__global__ void k_split(const float* __restrict__ a, __nv_bfloat16* __restrict__ hi,
                        __nv_bfloat16* __restrict__ lo, int n) {
    int i = blockIdx.x * blockDim.x + threadIdx.x;
    if (i >= n) return;
    float v = a[i];
    __nv_bfloat16 h = __float2bfloat16_rn(v);
    hi[i] = h;
    lo[i] = __float2bfloat16_rn(v - __bfloat162float(h));
}

// W[K,M] -> hiT/loT[M,K]
__global__ void k_prep_w(const float* __restrict__ W, __nv_bfloat16* __restrict__ hiT,
                         __nv_bfloat16* __restrict__ loT, int K, int M) {
    int i = blockIdx.x * blockDim.x + threadIdx.x;
    if (i >= K * M) return;
    int k = i / M, m = i % M;
    float v = W[i];
    __nv_bfloat16 h = __float2bfloat16_rn(v);
    hiT[(size_t)m * K + k] = h;
    loT[(size_t)m * K + k] = __float2bfloat16_rn(v - __bfloat162float(h));
}

// ---------------- mma.sync bf16 GEMM: C[Nr,M] = A[Nr,K] @ BT[M,K]^T ---------
// 128x128 CTA tile, 8 warps (2m x 4n), warp tile 64x32, K-chunk 32.
// 3 virtual passes: Ahi*Bhi + Alo*Bhi + Ahi*Blo accumulated in registers.
#define PAD 56            // bf16 per smem row (112B: 16B-aligned, conflict-free)
__global__ __launch_bounds__(256) void k_gemm_mma(
    const __nv_bfloat16* __restrict__ Ahi, const __nv_bfloat16* __restrict__ Alo,
    const __nv_bfloat16* __restrict__ BhiT, const __nv_bfloat16* __restrict__ BloT,
    float* __restrict__ C, int Nrows, int K, int M)
{
    __shared__ __align__(16) __nv_bfloat16 sA[128 * PAD];
    __shared__ __align__(16) __nv_bfloat16 sB[128 * PAD];

    int tid = threadIdx.x;
    int wid = tid >> 5, lane = tid & 31;
    int wm = wid & 1, wn = wid >> 1;
    int row0 = blockIdx.y * 128;
    int col0 = blockIdx.x * 128;
    int mBase = wm * 64, nBase = wn * 32;
    int g = lane >> 2;          // 0..7
    int cw = lane & 3;          // word (2-bf16) index

    float acc[4][4][4];
    #pragma unroll
    for (int a = 0; a < 4; a++)
        #pragma unroll
        for (int b = 0; b < 4; b++)
            #pragma unroll
            for (int c = 0; c < 4; c++) acc[a][b][c] = 0.f;

    // loader mapping: thread -> (row, 32B half)
    int lr = tid >> 1;
    int lh = tid & 1;

    int nk = K / 32;
    int NC = 3 * nk;

    for (int cidx = 0; cidx < NC; cidx++) {
        int pass = cidx / nk;
        int kofs = (cidx - pass * nk) * 32;
        const __nv_bfloat16* Ap = (pass == 1) ? Alo : Ahi;
        const __nv_bfloat16* Bp = (pass == 2) ? BloT : BhiT;

        __syncthreads();
        {
            uint4 v0 = make_uint4(0u, 0u, 0u, 0u), v1 = v0;
            int gr = row0 + lr;
            if (gr < Nrows) {
                const uint4* p = (const uint4*)(Ap + (size_t)gr * K + kofs + lh * 16);
                v0 = p[0]; v1 = p[1];
            }
            uint4* q = (uint4*)(sA + lr * PAD + lh * 16);
            q[0] = v0; q[1] = v1;

            const uint4* pb = (const uint4*)(Bp + (size_t)(col0 + lr) * K + kofs + lh * 16);
            uint4* qb = (uint4*)(sB + lr * PAD + lh * 16);
            qb[0] = pb[0]; qb[1] = pb[1];
        }
        __syncthreads();

        #pragma unroll
        for (int ks = 0; ks < 2; ks++) {
            int kw = ks * 8;      // word offset of this k16 step
            uint32_t af[4][4];
            #pragma unroll
            for (int mi = 0; mi < 4; mi++) {
                const uint32_t* p0 = (const uint32_t*)(sA + (mBase + mi * 16 + g) * PAD);
                const uint32_t* p1 = (const uint32_t*)(sA + (mBase + mi * 16 + g + 8) * PAD);
                af[mi][0] = p0[kw + cw];
                af[mi][1] = p1[kw + cw];
                af[mi][2] = p0[kw + cw + 4];
                af[mi][3] = p1[kw + cw + 4];
            }
            uint32_t bf[4][2];
            #pragma unroll
            for (int ni = 0; ni < 4; ni++) {
                const uint32_t* p = (const uint32_t*)(sB + (nBase + ni * 8 + g) * PAD);
                bf[ni][0] = p[kw + cw];
                bf[ni][1] = p[kw + cw + 4];
            }
            #pragma unroll
            for (int mi = 0; mi < 4; mi++)
                #pragma unroll
                for (int ni = 0; ni < 4; ni++) {
                    float* d = acc[mi][ni];
                    asm volatile(
                        "mma.sync.aligned.m16n8k16.row.col.f32.bf16.bf16.f32 "
                        "{%0,%1,%2,%3}, {%4,%5,%6,%7}, {%8,%9}, {%0,%1,%2,%3};"
                        : "+f"(d[0]), "+f"(d[1]), "+f"(d[2]), "+f"(d[3])
                        : "r"(af[mi][0]), "r"(af[mi][1]), "r"(af[mi][2]), "r"(af[mi][3]),
                          "r"(bf[ni][0]), "r"(bf[ni][1]));
                }
        }
    }

    // epilogue
    #pragma unroll
    for (int mi = 0; mi < 4; mi++) {
        int r0 = row0 + mBase + mi * 16 + g;
        #pragma unroll
        for (int ni = 0; ni < 4; ni++) {
            int cc = col0 + nBase + ni * 8 + cw * 2;
            if (r0 < Nrows)
                *(float2*)(C + (size_t)r0 * M + cc) = make_float2(acc[mi][ni][0], acc[mi][ni][1]);
            if (r0 + 8 < Nrows)
                *(float2*)(C + (size_t)(r0 + 8) * M + cc) = make_float2(acc[mi][ni][2], acc[mi][ni][3]);
        }
    }
}

// ---------------- edge-index dtype detection + decode -----------------------
__global__ void k_detect(const int* __restrict__ w) {
    __shared__ int s;
    if (threadIdx.x == 0) s = 0;
    __syncthreads();
    int acc = 0;
    for (int i = threadIdx.x; i < 2048; i += 256) acc |= w[2 * i + 1];
    atomicOr(&s, acc);
    __syncthreads();
    if (threadIdx.x == 0) g_is64 = (s == 0) ? 1 : 0;
}

__global__ void k_edges(const int* __restrict__ w) {
    int i = blockIdx.x * blockDim.x + threadIdx.x;
    if (i >= NE) return;
    int s, d;
    if (g_is64) { s = w[2 * i]; d = w[2 * (NE + i)]; }
    else        { s = w[i];     d = w[NE + i]; }
    if ((unsigned)s >= NN) s = 0;
    if ((unsigned)d >= NN) d = 0;
    g_src[i] = s;
    g_dst[i] = d;
}

__global__ void k_init_nodes() {
    int i = blockIdx.x * blockDim.x + threadIdx.x;
    if (i < NN) { g_nmax[i] = -3.0e38f; g_den[i] = 0.0f; }
}

__global__ void k_zero4(float4* __restrict__ p, int n4) {
    int i = blockIdx.x * blockDim.x + threadIdx.x;
    if (i < n4) p[i] = make_float4(0.f, 0.f, 0.f, 0.f);
}

// ---------------- GATv2 edge kernels ---------------------------------------
__device__ __forceinline__ void atomicMaxF(float* addr, float val) {
    int old = __float_as_int(*addr);
    while (__int_as_float(old) < val) {
        int prev = atomicCAS((int*)addr, old, __float_as_int(val));
        if (prev == old) break;
        old = prev;
    }
}

__global__ void k_edge_att(const float* __restrict__ att) {
    int gt = blockIdx.x * blockDim.x + threadIdx.x;
    int edge = gt >> 5;
    int lane = gt & 31;
    if (edge >= NE) return;
    int s = g_src[edge], d = g_dst[edge];
    const float4* ps = (const float4*)(g_xl + (size_t)s * DE);
    const float4* pd = (const float4*)(g_xr + (size_t)d * DE);
    const float4* pt = (const float4*)att;
    float acc = 0.f;
    #pragma unroll
    for (int i = 0; i < DE / 128; i++) {
        int k = i * 32 + lane;
        float4 a = ps[k], b = pd[k], w = pt[k];
        float v;
        v = a.x + b.x; v = (v > 0.f) ? v : 0.2f * v; acc += v * w.x;
        v = a.y + b.y; v = (v > 0.f) ? v : 0.2f * v; acc += v * w.y;
        v = a.z + b.z; v = (v > 0.f) ? v : 0.2f * v; acc += v * w.z;
        v = a.w + b.w; v = (v > 0.f) ? v : 0.2f * v; acc += v * w.w;
    }
    #pragma unroll
    for (int o = 16; o; o >>= 1) acc += __shfl_xor_sync(0xffffffffu, acc, o);
    if (lane == 0) {
        g_e[edge] = acc;
        atomicMaxF(&g_nmax[d], acc);
    }
}

__global__ void k_edge_w() {
    int i = blockIdx.x * blockDim.x + threadIdx.x;
    if (i >= NE) return;
    int d = g_dst[i];
    float w = expf(g_e[i] - g_nmax[d]);
    g_w[i] = w;
    atomicAdd(&g_den[d], w);
}

__global__ void k_edge_agg() {
    int gt = blockIdx.x * blockDim.x + threadIdx.x;
    int edge = gt >> 5;
    int lane = gt & 31;
    if (edge >= NE) return;
    int s = g_src[edge], d = g_dst[edge];
    float alpha = g_w[edge] / (g_den[d] + 1e-16f);
    const float4* ps = (const float4*)(g_xl + (size_t)s * DE);
    float4* pa = (float4*)(g_agg + (size_t)d * DE);
    #pragma unroll
    for (int i = 0; i < DE / 128; i++) {
        int k = i * 32 + lane;
        float4 v = ps[k];
        asm volatile("red.global.add.v4.f32 [%0], {%1, %2, %3, %4};"
                     :: "l"(pa + k),
                        "f"(alpha * v.x), "f"(alpha * v.y),
                        "f"(alpha * v.z), "f"(alpha * v.w)
                     : "memory");
    }
}

__global__ void k_finish(const float* __restrict__ bias) {
    int i = blockIdx.x * blockDim.x + threadIdx.x;
    int n4 = NN * DE / 4;
    if (i >= n4) return;
    float4 a = ((const float4*)g_agg)[i];
    float4 b = ((const float4*)bias)[i & (DE / 4 - 1)];
    float4 r;
    r.x = tanhf(a.x + b.x); r.y = tanhf(a.y + b.y);
    r.z = tanhf(a.z + b.z); r.w = tanhf(a.w + b.w);
    ((float4*)g_h)[i] = r;
}

// ---------------- MLP kernels ----------------------------------------------
__global__ void k_bias_leaky(float* __restrict__ p, const float* __restrict__ c) {
    int i = blockIdx.x * blockDim.x + threadIdx.x;
    int n4 = NN * DH / 4;
    if (i >= n4) return;
    float4 v = ((const float4*)p)[i];
    float4 b = ((const float4*)c)[i & (DH / 4 - 1)];
    float4 r;
    float t;
    t = v.x + b.x; r.x = (t > 0.f) ? t : 0.1f * t;
    t = v.y + b.y; r.y = (t > 0.f) ? t : 0.1f * t;
    t = v.z + b.z; r.z = (t > 0.f) ? t : 0.1f * t;
    t = v.w + b.w; r.w = (t > 0.f) ? t : 0.1f * t;
    ((float4*)p)[i] = r;
}

__global__ void k_dot3(const float* __restrict__ A3, const float* __restrict__ c3) {
    int gt = blockIdx.x * blockDim.x + threadIdx.x;
    int n = gt >> 5;
    int lane = gt & 31;
    if (n >= NN) return;
    const float4* pm = (const float4*)(g_m2 + (size_t)n * DH);
    const float4* pw = (const float4*)A3;
    float acc = 0.f;
    #pragma unroll
    for (int i = 0; i < DH / 128; i++) {
        int k = i * 32 + lane;
        float4 m = pm[k], w = pw[k];
        acc += m.x * w.x + m.y * w.y + m.z * w.z + m.w * w.w;
    }
    #pragma unroll
    for (int o = 16; o; o >>= 1) acc += __shfl_xor_sync(0xffffffffu, acc, o);
    if (lane == 0) g_logit[n] = acc + c3[0];
}

__global__ void k_softmax(float* __restrict__ out) {
    __shared__ float sh[1024];
    int t = threadIdx.x;
    float m = -3.0e38f;
    for (int i = t; i < NN; i += 1024) m = fmaxf(m, g_logit[i]);
    sh[t] = m; __syncthreads();
    for (int s = 512; s; s >>= 1) { if (t < s) sh[t] = fmaxf(sh[t], sh[t + s]); __syncthreads(); }
    float gm = sh[0]; __syncthreads();
    float sum = 0.f;
    for (int i = t; i < NN; i += 1024) sum += expf(g_logit[i] - gm);
    sh[t] = sum; __syncthreads();
    for (int s = 512; s; s >>= 1) { if (t < s) sh[t] += sh[t + s]; __syncthreads(); }
    float gs = sh[0];
    for (int i = t; i < NN; i += 1024) out[i] = expf(g_logit[i] - gm) / gs;
}

// ---------------- host side -------------------------------------------------
static __nv_bfloat16 *s_ahi, *s_alo, *s_whi, *s_wlo;

static void tc_gemm(const float* W, int K, int M, float* Cout) {
    k_prep_w<<<(K * M + 255) / 256, 256>>>(W, s_whi, s_wlo, K, M);
    dim3 g(M / 128, (NN + 127) / 128);
    k_gemm_mma<<<g, 256>>>(s_ahi, s_alo, s_whi, s_wlo, Cout, NN, K, M);
}

static void gat_layer(const float* hin, int din,
                      const float* Wl, const float* Wr,
                      const float* att, const float* bias,
                      float* xl, float* xr, float* agg) {
    k_split<<<(NN * din + 255) / 256, 256>>>(hin, s_ahi, s_alo, NN * din);
    tc_gemm(Wl, din, DE, xl);
    tc_gemm(Wr, din, DE, xr);
    k_init_nodes<<<(NN + 255) / 256, 256>>>();
    k_zero4<<<(NN * DE / 4 + 255) / 256, 256>>>((float4*)agg, NN * DE / 4);
    k_edge_att<<<(NE * 32 + 255) / 256, 256>>>(att);
    k_edge_w<<<(NE + 255) / 256, 256>>>();
    k_edge_agg<<<(NE * 32 + 255) / 256, 256>>>();
    k_finish<<<(NN * DE / 4 + 255) / 256, 256>>>(bias);
}

extern "C" void kernel_launch(void* const* d_in, const int* in_sizes, int n_in,
                              void* d_out, int out_size) {
    const float* x   = (const float*)d_in[0];
    const int*   ei  = (const int*)d_in[1];
    const float* Wl1 = (const float*)d_in[2];
    const float* Wr1 = (const float*)d_in[3];
    const float* at1 = (const float*)d_in[4];
    const float* b1  = (const float*)d_in[5];
    const float* Wl2 = (const float*)d_in[6];
    const float* Wr2 = (const float*)d_in[7];
    const float* at2 = (const float*)d_in[8];
    const float* b2  = (const float*)d_in[9];
    const float* Wl3 = (const float*)d_in[10];
    const float* Wr3 = (const float*)d_in[11];
    const float* at3 = (const float*)d_in[12];
    const float* b3  = (const float*)d_in[13];
    const float* A1  = (const float*)d_in[14];
    const float* c1  = (const float*)d_in[15];
    const float* A2  = (const float*)d_in[16];
    const float* c2  = (const float*)d_in[17];
    const float* A3  = (const float*)d_in[18];
    const float* c3  = (const float*)d_in[19];
    float* out = (float*)d_out;

    float *xl, *xr, *h, *agg, *m1, *m2;
    cudaGetSymbolAddress((void**)&xl,  g_xl);
    cudaGetSymbolAddress((void**)&xr,  g_xr);
    cudaGetSymbolAddress((void**)&h,   g_h);
    cudaGetSymbolAddress((void**)&agg, g_agg);
    cudaGetSymbolAddress((void**)&m1,  g_m1);
    cudaGetSymbolAddress((void**)&m2,  g_m2);
    cudaGetSymbolAddress((void**)&s_ahi, g_ahi);
    cudaGetSymbolAddress((void**)&s_alo, g_alo);
    cudaGetSymbolAddress((void**)&s_whi, g_whi);
    cudaGetSymbolAddress((void**)&s_wlo, g_wlo);

    k_detect<<<1, 256>>>(ei);
    k_edges<<<(NE + 255) / 256, 256>>>(ei);

    gat_layer(x, DI, Wl1, Wr1, at1, b1, xl, xr, agg);
    gat_layer(h, DE, Wl2, Wr2, at2, b2, xl, xr, agg);
    gat_layer(h, DE, Wl3, Wr3, at3, b3, xl, xr, agg);

    // MLP
    k_split<<<(NN * DE + 255) / 256, 256>>>(h, s_ahi, s_alo, NN * DE);
    tc_gemm(A1, DE, DH, m1);
    k_bias_leaky<<<(NN * DH / 4 + 255) / 256, 256>>>(m1, c1);
    k_split<<<(NN * DH + 255) / 256, 256>>>(m1, s_ahi, s_alo, NN * DH);
    tc_gemm(A2, DH, DH, m2);
    k_bias_leaky<<<(NN * DH / 4 + 255) / 256, 256>>>(m2, c2);
    k_dot3<<<(NN * 32 + 255) / 256, 256>>>(A3, c3);
    k_softmax<<<1, 1024>>>(out);
}

// round 6
// speedup vs baseline: 1.2983x; 1.1862x over previous
#include <cuda_runtime.h>
#include <cuda_bf16.h>
#include <math.h>
#include <stdint.h>

#define NN 10000
#define NE 160000
#define DI 128
#define DE 512
#define DH 256

// ---------------- scratch (device globals; no allocation allowed) ----------
__device__ __align__(16) float g_xl[NN * DE];
__device__ __align__(16) float g_xr[NN * DE];
__device__ float g_e[NE];
__device__ int   g_src[NE];
__device__ int   g_dst[NE];
__device__ int   g_deg[NN];
__device__ int   g_rs[NN + 1];
__device__ int   g_cur[NN];
__device__ int   g_csrc[NE];
__device__ __align__(16) float g_m1[NN * DH];
__device__ __align__(16) float g_m2[NN * DH];
__device__ float g_logit[NN];
__device__ int   g_is64;
// bf16 hi/lo operands (A = activations, W = weights transposed)
__device__ __align__(16) __nv_bfloat16 g_ahi[NN * DE];
__device__ __align__(16) __nv_bfloat16 g_alo[NN * DE];
__device__ __align__(16) __nv_bfloat16 g_whi[DE * DE];
__device__ __align__(16) __nv_bfloat16 g_wlo[DE * DE];

// ---------------- edge decode + CSR build ----------------------------------
__global__ void k_detect(const int* __restrict__ w) {
    __shared__ int s;
    if (threadIdx.x == 0) s = 0;
    __syncthreads();
    int acc = 0;
    for (int i = threadIdx.x; i < 2048; i += 256) acc |= w[2 * i + 1];
    atomicOr(&s, acc);
    __syncthreads();
    if (threadIdx.x == 0) g_is64 = (s == 0) ? 1 : 0;
}

__global__ void k_edges(const int* __restrict__ w) {
    int i = blockIdx.x * blockDim.x + threadIdx.x;
    if (i >= NE) return;
    int s, d;
    if (g_is64) { s = w[2 * i]; d = w[2 * (NE + i)]; }
    else        { s = w[i];     d = w[NE + i]; }
    if ((unsigned)s >= NN) s = 0;
    if ((unsigned)d >= NN) d = 0;
    g_src[i] = s;
    g_dst[i] = d;
}

__global__ void k_zero_deg() {
    int i = blockIdx.x * blockDim.x + threadIdx.x;
    if (i < NN) g_deg[i] = 0;
}

__global__ void k_hist() {
    int i = blockIdx.x * blockDim.x + threadIdx.x;
    if (i < NE) atomicAdd(&g_deg[g_dst[i]], 1);
}

__global__ void k_scan() {
    __shared__ int s[1024];
    __shared__ int sbase;
    int t = threadIdx.x;
    if (t == 0) sbase = 0;
    __syncthreads();
    for (int chunk = 0; chunk < NN; chunk += 1024) {
        int idx = chunk + t;
        int v = (idx < NN) ? g_deg[idx] : 0;
        s[t] = v;
        __syncthreads();
        for (int off = 1; off < 1024; off <<= 1) {
            int u = (t >= off) ? s[t - off] : 0;
            __syncthreads();
            s[t] += u;
            __syncthreads();
        }
        if (idx < NN) g_rs[idx] = sbase + s[t] - v;
        int tot = s[1023];
        __syncthreads();
        if (t == 0) sbase += tot;
        __syncthreads();
    }
    if (t == 0) g_rs[NN] = sbase;
}

__global__ void k_setcur() {
    int i = blockIdx.x * blockDim.x + threadIdx.x;
    if (i < NN) g_cur[i] = g_rs[i];
}

__global__ void k_scatter() {
    int i = blockIdx.x * blockDim.x + threadIdx.x;
    if (i >= NE) return;
    int pos = atomicAdd(&g_cur[g_dst[i]], 1);
    g_csrc[pos] = g_src[i];
}

// ---------------- hi/lo split ------------------------------------------------
__global__ void k_split(const float* __restrict__ a, __nv_bfloat16* __restrict__ hi,
                        __nv_bfloat16* __restrict__ lo, int n) {
    int i = blockIdx.x * blockDim.x + threadIdx.x;
    if (i >= n) return;
    float v = a[i];
    __nv_bfloat16 h = __float2bfloat16_rn(v);
    hi[i] = h;
    lo[i] = __float2bfloat16_rn(v - __bfloat162float(h));
}

// W[K,M] -> hiT/loT[M,K]
__global__ void k_prep_w(const float* __restrict__ W, __nv_bfloat16* __restrict__ hiT,
                         __nv_bfloat16* __restrict__ loT, int K, int M) {
    int i = blockIdx.x * blockDim.x + threadIdx.x;
    if (i >= K * M) return;
    int k = i / M, m = i % M;
    float v = W[i];
    __nv_bfloat16 h = __float2bfloat16_rn(v);
    hiT[(size_t)m * K + k] = h;
    loT[(size_t)m * K + k] = __float2bfloat16_rn(v - __bfloat162float(h));
}

// ---------------- mma.sync bf16 GEMM (3-pass hi/lo) -------------------------
#define PAD 56
__global__ __launch_bounds__(256) void k_gemm_mma(
    const __nv_bfloat16* __restrict__ Ahi, const __nv_bfloat16* __restrict__ Alo,
    const __nv_bfloat16* __restrict__ BhiT, const __nv_bfloat16* __restrict__ BloT,
    float* __restrict__ C, int Nrows, int K, int M)
{
    __shared__ __align__(16) __nv_bfloat16 sA[128 * PAD];
    __shared__ __align__(16) __nv_bfloat16 sB[128 * PAD];

    int tid = threadIdx.x;
    int wid = tid >> 5, lane = tid & 31;
    int wm = wid & 1, wn = wid >> 1;
    int row0 = blockIdx.y * 128;
    int col0 = blockIdx.x * 128;
    int mBase = wm * 64, nBase = wn * 32;
    int g = lane >> 2;
    int cw = lane & 3;

    float acc[4][4][4];
    #pragma unroll
    for (int a = 0; a < 4; a++)
        #pragma unroll
        for (int b = 0; b < 4; b++)
            #pragma unroll
            for (int c = 0; c < 4; c++) acc[a][b][c] = 0.f;

    int lr = tid >> 1;
    int lh = tid & 1;
    int nk = K / 32;
    int NC = 3 * nk;

    for (int cidx = 0; cidx < NC; cidx++) {
        int pass = cidx / nk;
        int kofs = (cidx - pass * nk) * 32;
        const __nv_bfloat16* Ap = (pass == 1) ? Alo : Ahi;
        const __nv_bfloat16* Bp = (pass == 2) ? BloT : BhiT;

        __syncthreads();
        {
            uint4 v0 = make_uint4(0u, 0u, 0u, 0u), v1 = v0;
            int gr = row0 + lr;
            if (gr < Nrows) {
                const uint4* p = (const uint4*)(Ap + (size_t)gr * K + kofs + lh * 16);
                v0 = p[0]; v1 = p[1];
            }
            uint4* q = (uint4*)(sA + lr * PAD + lh * 16);
            q[0] = v0; q[1] = v1;

            const uint4* pb = (const uint4*)(Bp + (size_t)(col0 + lr) * K + kofs + lh * 16);
            uint4* qb = (uint4*)(sB + lr * PAD + lh * 16);
            qb[0] = pb[0]; qb[1] = pb[1];
        }
        __syncthreads();

        #pragma unroll
        for (int ks = 0; ks < 2; ks++) {
            int kw = ks * 8;
            uint32_t af[4][4];
            #pragma unroll
            for (int mi = 0; mi < 4; mi++) {
                const uint32_t* p0 = (const uint32_t*)(sA + (mBase + mi * 16 + g) * PAD);
                const uint32_t* p1 = (const uint32_t*)(sA + (mBase + mi * 16 + g + 8) * PAD);
                af[mi][0] = p0[kw + cw];
                af[mi][1] = p1[kw + cw];
                af[mi][2] = p0[kw + cw + 4];
                af[mi][3] = p1[kw + cw + 4];
            }
            uint32_t bf[4][2];
            #pragma unroll
            for (int ni = 0; ni < 4; ni++) {
                const uint32_t* p = (const uint32_t*)(sB + (nBase + ni * 8 + g) * PAD);
                bf[ni][0] = p[kw + cw];
                bf[ni][1] = p[kw + cw + 4];
            }
            #pragma unroll
            for (int mi = 0; mi < 4; mi++)
                #pragma unroll
                for (int ni = 0; ni < 4; ni++) {
                    float* d = acc[mi][ni];
                    asm volatile(
                        "mma.sync.aligned.m16n8k16.row.col.f32.bf16.bf16.f32 "
                        "{%0,%1,%2,%3}, {%4,%5,%6,%7}, {%8,%9}, {%0,%1,%2,%3};"
                        : "+f"(d[0]), "+f"(d[1]), "+f"(d[2]), "+f"(d[3])
                        : "r"(af[mi][0]), "r"(af[mi][1]), "r"(af[mi][2]), "r"(af[mi][3]),
                          "r"(bf[ni][0]), "r"(bf[ni][1]));
                }
        }
    }

    #pragma unroll
    for (int mi = 0; mi < 4; mi++) {
        int r0 = row0 + mBase + mi * 16 + g;
        #pragma unroll
        for (int ni = 0; ni < 4; ni++) {
            int cc = col0 + nBase + ni * 8 + cw * 2;
            if (r0 < Nrows)
                *(float2*)(C + (size_t)r0 * M + cc) = make_float2(acc[mi][ni][0], acc[mi][ni][1]);
            if (r0 + 8 < Nrows)
                *(float2*)(C + (size_t)(r0 + 8) * M + cc) = make_float2(acc[mi][ni][2], acc[mi][ni][3]);
        }
    }
}

// ---------------- fused GATv2 edge kernel: one warp per dst -----------------
// pass1: e_i = att.leaky(xl[src]+xr[d]); exact max (sequential)
// pass2: w=exp(e-m), den+=w, acc += w*xl[src]
// epilogue: h=tanh(acc/(den+eps)+bias) -> bf16 hi/lo (next GEMM input)
__global__ __launch_bounds__(256) void k_gat_edge(const float* __restrict__ att,
                                                  const float* __restrict__ bias) {
    int gw = (blockIdx.x * 256 + threadIdx.x) >> 5;
    int lane = threadIdx.x & 31;
    if (gw >= NN) return;
    int d = gw;
    int rs = g_rs[d], re = g_rs[d + 1];

    float4 xr4[4], at4[4];
    const float4* pxr = (const float4*)(g_xr + (size_t)d * DE);
    const float4* pat = (const float4*)att;
    #pragma unroll
    for (int j = 0; j < 4; j++) {
        xr4[j] = pxr[j * 32 + lane];
        at4[j] = pat[j * 32 + lane];
    }

    float m = -3.0e38f;
    for (int e = rs; e < re; e++) {
        int s = g_csrc[e];
        const float4* pxl = (const float4*)(g_xl + (size_t)s * DE);
        float acc = 0.f;
        #pragma unroll
        for (int j = 0; j < 4; j++) {
            float4 a = pxl[j * 32 + lane];
            float v;
            v = a.x + xr4[j].x; v = v > 0.f ? v : 0.2f * v; acc += v * at4[j].x;
            v = a.y + xr4[j].y; v = v > 0.f ? v : 0.2f * v; acc += v * at4[j].y;
            v = a.z + xr4[j].z; v = v > 0.f ? v : 0.2f * v; acc += v * at4[j].z;
            v = a.w + xr4[j].w; v = v > 0.f ? v : 0.2f * v; acc += v * at4[j].w;
        }
        #pragma unroll
        for (int o = 16; o; o >>= 1) acc += __shfl_xor_sync(0xffffffffu, acc, o);
        if (lane == 0) g_e[e] = acc;
        m = fmaxf(m, acc);
    }

    float den = 0.f;
    float accf[16];
    #pragma unroll
    for (int j = 0; j < 16; j++) accf[j] = 0.f;

    for (int e = rs; e < re; e++) {
        int s = g_csrc[e];
        float w = expf(g_e[e] - m);
        den += w;
        const float4* pxl = (const float4*)(g_xl + (size_t)s * DE);
        #pragma unroll
        for (int j = 0; j < 4; j++) {
            float4 a = pxl[j * 32 + lane];
            accf[4 * j + 0] += w * a.x;
            accf[4 * j + 1] += w * a.y;
            accf[4 * j + 2] += w * a.z;
            accf[4 * j + 3] += w * a.w;
        }
    }

    float inv = 1.0f / (den + 1e-16f);
    const float4* pb = (const float4*)bias;
    __nv_bfloat16* ph = g_ahi + (size_t)d * DE;
    __nv_bfloat16* pl = g_alo + (size_t)d * DE;
    #pragma unroll
    for (int j = 0; j < 4; j++) {
        float4 b = pb[j * 32 + lane];
        float t0 = tanhf(accf[4 * j + 0] * inv + b.x);
        float t1 = tanhf(accf[4 * j + 1] * inv + b.y);
        float t2 = tanhf(accf[4 * j + 2] * inv + b.z);
        float t3 = tanhf(accf[4 * j + 3] * inv + b.w);
        __nv_bfloat162 h01 = __floats2bfloat162_rn(t0, t1);
        __nv_bfloat162 h23 = __floats2bfloat162_rn(t2, t3);
        float l0 = t0 - __bfloat162float(__low2bfloat16(h01));
        float l1 = t1 - __bfloat162float(__high2bfloat16(h01));
        float l2 = t2 - __bfloat162float(__low2bfloat16(h23));
        float l3 = t3 - __bfloat162float(__high2bfloat16(h23));
        __nv_bfloat162 q01 = __floats2bfloat162_rn(l0, l1);
        __nv_bfloat162 q23 = __floats2bfloat162_rn(l2, l3);
        uint2 uh, ul;
        uh.x = *(uint32_t*)&h01; uh.y = *(uint32_t*)&h23;
        ul.x = *(uint32_t*)&q01; ul.y = *(uint32_t*)&q23;
        ((uint2*)ph)[j * 32 + lane] = uh;
        ((uint2*)pl)[j * 32 + lane] = ul;
    }
}

// ---------------- MLP kernels ----------------------------------------------
// v = leaky(p + c); write fp32 back + bf16 hi/lo
__global__ void k_blsplit(float* __restrict__ p, const float* __restrict__ c,
                          __nv_bfloat16* __restrict__ hi, __nv_bfloat16* __restrict__ lo,
                          int dim, int n) {
    int i = blockIdx.x * blockDim.x + threadIdx.x;
    if (i >= n) return;
    float v = p[i] + c[i % dim];
    v = (v > 0.f) ? v : 0.1f * v;
    p[i] = v;
    __nv_bfloat16 h = __float2bfloat16_rn(v);
    hi[i] = h;
    lo[i] = __float2bfloat16_rn(v - __bfloat162float(h));
}

__global__ void k_dot3(const float* __restrict__ A3, const float* __restrict__ c3) {
    int gt = blockIdx.x * blockDim.x + threadIdx.x;
    int n = gt >> 5;
    int lane = gt & 31;
    if (n >= NN) return;
    const float4* pm = (const float4*)(g_m2 + (size_t)n * DH);
    const float4* pw = (const float4*)A3;
    float acc = 0.f;
    #pragma unroll
    for (int i = 0; i < DH / 128; i++) {
        int k = i * 32 + lane;
        float4 m = pm[k], w = pw[k];
        acc += m.x * w.x + m.y * w.y + m.z * w.z + m.w * w.w;
    }
    #pragma unroll
    for (int o = 16; o; o >>= 1) acc += __shfl_xor_sync(0xffffffffu, acc, o);
    if (lane == 0) g_logit[n] = acc + c3[0];
}

__global__ void k_softmax(float* __restrict__ out) {
    __shared__ float sh[1024];
    int t = threadIdx.x;
    float m = -3.0e38f;
    for (int i = t; i < NN; i += 1024) m = fmaxf(m, g_logit[i]);
    sh[t] = m; __syncthreads();
    for (int s = 512; s; s >>= 1) { if (t < s) sh[t] = fmaxf(sh[t], sh[t + s]); __syncthreads(); }
    float gm = sh[0]; __syncthreads();
    float sum = 0.f;
    for (int i = t; i < NN; i += 1024) sum += expf(g_logit[i] - gm);
    sh[t] = sum; __syncthreads();
    for (int s = 512; s; s >>= 1) { if (t < s) sh[t] += sh[t + s]; __syncthreads(); }
    float gs = sh[0];
    for (int i = t; i < NN; i += 1024) out[i] = expf(g_logit[i] - gm) / gs;
}

// ---------------- host side -------------------------------------------------
static __nv_bfloat16 *s_ahi, *s_alo, *s_whi, *s_wlo;

static void tc_gemm(const float* W, int K, int M, float* Cout) {
    k_prep_w<<<(K * M + 255) / 256, 256>>>(W, s_whi, s_wlo, K, M);
    dim3 g(M / 128, (NN + 127) / 128);
    k_gemm_mma<<<g, 256>>>(s_ahi, s_alo, s_whi, s_wlo, Cout, NN, K, M);
}

static void gat_layer(int din, const float* Wl, const float* Wr,
                      const float* att, const float* bias,
                      float* xl, float* xr) {
    // consumes s_ahi/s_alo (din-dim rows); overwrites them with this layer's output
    tc_gemm(Wl, din, DE, xl);
    tc_gemm(Wr, din, DE, xr);
    k_gat_edge<<<(NN * 32 + 255) / 256, 256>>>(att, bias);
}

extern "C" void kernel_launch(void* const* d_in, const int* in_sizes, int n_in,
                              void* d_out, int out_size) {
    const float* x   = (const float*)d_in[0];
    const int*   ei  = (const int*)d_in[1];
    const float* Wl1 = (const float*)d_in[2];
    const float* Wr1 = (const float*)d_in[3];
    const float* at1 = (const float*)d_in[4];
    const float* b1  = (const float*)d_in[5];
    const float* Wl2 = (const float*)d_in[6];
    const float* Wr2 = (const float*)d_in[7];
    const float* at2 = (const float*)d_in[8];
    const float* b2  = (const float*)d_in[9];
    const float* Wl3 = (const float*)d_in[10];
    const float* Wr3 = (const float*)d_in[11];
    const float* at3 = (const float*)d_in[12];
    const float* b3  = (const float*)d_in[13];
    const float* A1  = (const float*)d_in[14];
    const float* c1  = (const float*)d_in[15];
    const float* A2  = (const float*)d_in[16];
    const float* c2  = (const float*)d_in[17];
    const float* A3  = (const float*)d_in[18];
    const float* c3  = (const float*)d_in[19];
    float* out = (float*)d_out;

    float *xl, *xr, *m1, *m2;
    cudaGetSymbolAddress((void**)&xl,  g_xl);
    cudaGetSymbolAddress((void**)&xr,  g_xr);
    cudaGetSymbolAddress((void**)&m1,  g_m1);
    cudaGetSymbolAddress((void**)&m2,  g_m2);
    cudaGetSymbolAddress((void**)&s_ahi, g_ahi);
    cudaGetSymbolAddress((void**)&s_alo, g_alo);
    cudaGetSymbolAddress((void**)&s_whi, g_whi);
    cudaGetSymbolAddress((void**)&s_wlo, g_wlo);

    // edges + CSR by dst
    k_detect<<<1, 256>>>(ei);
    k_edges<<<(NE + 255) / 256, 256>>>(ei);
    k_zero_deg<<<(NN + 255) / 256, 256>>>();
    k_hist<<<(NE + 255) / 256, 256>>>();
    k_scan<<<1, 1024>>>();
    k_setcur<<<(NN + 255) / 256, 256>>>();
    k_scatter<<<(NE + 255) / 256, 256>>>();

    // layer 1 input split
    k_split<<<(NN * DI + 255) / 256, 256>>>(x, s_ahi, s_alo, NN * DI);

    gat_layer(DI, Wl1, Wr1, at1, b1, xl, xr);
    gat_layer(DE, Wl2, Wr2, at2, b2, xl, xr);
    gat_layer(DE, Wl3, Wr3, at3, b3, xl, xr);

    // MLP (consumes s_ahi/s_alo holding layer-3 output)
    tc_gemm(A1, DE, DH, m1);
    k_blsplit<<<(NN * DH + 255) / 256, 256>>>(m1, c1, s_ahi, s_alo, DH, NN * DH);
    tc_gemm(A2, DH, DH, m2);
    k_blsplit<<<(NN * DH + 255) / 256, 256>>>(m2, c2, s_ahi, s_alo, DH, NN * DH);
    k_dot3<<<(NN * 32 + 255) / 256, 256>>>(A3, c3);
    k_softmax<<<1, 1024>>>(out);
}

// round 7
// speedup vs baseline: 1.8871x; 1.4535x over previous
#include <cuda_runtime.h>
#include <cuda_bf16.h>
#include <math.h>
#include <stdint.h>

#define NN 10000
#define NE 160000
#define DI 128
#define DE 512
#define DH 256

// ---------------- scratch (device globals; no allocation allowed) ----------
__device__ __align__(16) float g_xlr[NN * 2 * DE];   // [node][xl(512) | xr(512)]
__device__ float g_e[NE];
__device__ int   g_src[NE];
__device__ int   g_dst[NE];
__device__ int   g_deg[NN];
__device__ int   g_rs[NN + 1];
__device__ int   g_cur[NN];
__device__ int   g_csrc[NE];
__device__ __align__(16) float g_m1[NN * DH];
__device__ __align__(16) float g_m2[NN * DH];
__device__ float g_logit[NN];
__device__ int   g_is64;
__device__ __align__(16) __nv_bfloat16 g_ahi[NN * DE];
__device__ __align__(16) __nv_bfloat16 g_alo[NN * DE];
__device__ __align__(16) __nv_bfloat16 g_whi[2 * DE * DE];
__device__ __align__(16) __nv_bfloat16 g_wlo[2 * DE * DE];

// ---------------- edge decode + CSR build ----------------------------------
__global__ void k_detect(const int* __restrict__ w) {
    __shared__ int s;
    if (threadIdx.x == 0) s = 0;
    __syncthreads();
    int acc = 0;
    for (int i = threadIdx.x; i < 2048; i += 256) acc |= w[2 * i + 1];
    atomicOr(&s, acc);
    __syncthreads();
    if (threadIdx.x == 0) g_is64 = (s == 0) ? 1 : 0;
}

__global__ void k_edges(const int* __restrict__ w) {
    int i = blockIdx.x * blockDim.x + threadIdx.x;
    if (i >= NE) return;
    int s, d;
    if (g_is64) { s = w[2 * i]; d = w[2 * (NE + i)]; }
    else        { s = w[i];     d = w[NE + i]; }
    if ((unsigned)s >= NN) s = 0;
    if ((unsigned)d >= NN) d = 0;
    g_src[i] = s;
    g_dst[i] = d;
}

__global__ void k_zero_deg() {
    int i = blockIdx.x * blockDim.x + threadIdx.x;
    if (i < NN) g_deg[i] = 0;
}

__global__ void k_hist() {
    int i = blockIdx.x * blockDim.x + threadIdx.x;
    if (i < NE) atomicAdd(&g_deg[g_dst[i]], 1);
}

__global__ void k_scan() {
    __shared__ int s[1024];
    __shared__ int sbase;
    int t = threadIdx.x;
    if (t == 0) sbase = 0;
    __syncthreads();
    for (int chunk = 0; chunk < NN; chunk += 1024) {
        int idx = chunk + t;
        int v = (idx < NN) ? g_deg[idx] : 0;
        s[t] = v;
        __syncthreads();
        for (int off = 1; off < 1024; off <<= 1) {
            int u = (t >= off) ? s[t - off] : 0;
            __syncthreads();
            s[t] += u;
            __syncthreads();
        }
        if (idx < NN) g_rs[idx] = sbase + s[t] - v;
        int tot = s[1023];
        __syncthreads();
        if (t == 0) sbase += tot;
        __syncthreads();
    }
    if (t == 0) g_rs[NN] = sbase;
}

__global__ void k_setcur() {
    int i = blockIdx.x * blockDim.x + threadIdx.x;
    if (i < NN) g_cur[i] = g_rs[i];
}

__global__ void k_scatter() {
    int i = blockIdx.x * blockDim.x + threadIdx.x;
    if (i >= NE) return;
    int pos = atomicAdd(&g_cur[g_dst[i]], 1);
    g_csrc[pos] = g_src[i];
}

// ---------------- hi/lo split ------------------------------------------------
__global__ void k_split(const float* __restrict__ a, __nv_bfloat16* __restrict__ hi,
                        __nv_bfloat16* __restrict__ lo, int n) {
    int i = blockIdx.x * blockDim.x + threadIdx.x;
    if (i >= n) return;
    float v = a[i];
    __nv_bfloat16 h = __float2bfloat16_rn(v);
    hi[i] = h;
    lo[i] = __float2bfloat16_rn(v - __bfloat162float(h));
}

// W[K,M] -> WT rows (m + rofs) of stride K
__global__ void k_prep_w(const float* __restrict__ W, __nv_bfloat16* __restrict__ hiT,
                         __nv_bfloat16* __restrict__ loT, int K, int M, int rofs) {
    int i = blockIdx.x * blockDim.x + threadIdx.x;
    if (i >= K * M) return;
    int k = i / M, m = i % M;
    float v = W[i];
    __nv_bfloat16 h = __float2bfloat16_rn(v);
    hiT[(size_t)(m + rofs) * K + k] = h;
    loT[(size_t)(m + rofs) * K + k] = __float2bfloat16_rn(v - __bfloat162float(h));
}

// ---------------- cp.async + ldmatrix bf16 GEMM (3-pass hi/lo) --------------
// C[Nr, M] = A[Nr, K] @ BT[M, K]^T ; 128x128 CTA tile, 8 warps (2m x 4n),
// BK=32 chunk; per chunk loads Ahi/Alo/Bhi/Blo and runs 3 passes.
#define TPAD 40                         // bf16 per smem row (80B, LDSM conflict-free)
#define TILE_E (128 * TPAD)             // elements per tile
#define STAGE_E (4 * TILE_E)            // 4 tiles per stage
#define SMEM_GEMM (2 * STAGE_E * 2)     // bytes (2 stages)

__device__ __forceinline__ void cpa16(uint32_t dst, const void* src, int sz) {
    asm volatile("cp.async.cg.shared.global [%0], [%1], 16, %2;"
                 :: "r"(dst), "l"(src), "r"(sz) : "memory");
}
__device__ __forceinline__ void cpa_commit() {
    asm volatile("cp.async.commit_group;" ::: "memory");
}
template<int N> __device__ __forceinline__ void cpa_wait() {
    asm volatile("cp.async.wait_group %0;" :: "n"(N) : "memory");
}
__device__ __forceinline__ void ldsm4(uint32_t* r, uint32_t addr) {
    asm volatile("ldmatrix.sync.aligned.m8n8.x4.shared.b16 {%0,%1,%2,%3}, [%4];"
                 : "=r"(r[0]), "=r"(r[1]), "=r"(r[2]), "=r"(r[3]) : "r"(addr));
}

__global__ __launch_bounds__(256) void k_gemm_mma(
    const __nv_bfloat16* __restrict__ Ahi, const __nv_bfloat16* __restrict__ Alo,
    const __nv_bfloat16* __restrict__ BhiT, const __nv_bfloat16* __restrict__ BloT,
    float* __restrict__ C, int Nrows, int K, int M)
{
    extern __shared__ __nv_bfloat16 smem[];
    uint32_t sb = (uint32_t)__cvta_generic_to_shared(smem);

    int tid = threadIdx.x;
    int wid = tid >> 5, lane = tid & 31;
    int wm = wid & 1, wn = wid >> 1;
    int row0 = blockIdx.y * 128;
    int col0 = blockIdx.x * 128;
    int mBase = wm * 64, nBase = wn * 32;
    int g = lane >> 2, cw = lane & 3;
    // ldmatrix lane addressing
    int mat = lane >> 3, r8 = lane & 7;
    int rsel = (mat & 1) * 8 + r8;
    int csel = (mat >> 1) * 8;

    float acc[4][4][4];
    #pragma unroll
    for (int a = 0; a < 4; a++)
        #pragma unroll
        for (int b = 0; b < 4; b++)
            #pragma unroll
            for (int c = 0; c < 4; c++) acc[a][b][c] = 0.f;

    int nk = K / 32;
    // loader: per tile 512 chunks of 16B; thread does chunks 2*tid, 2*tid+1
    int c0 = tid * 2;

    auto prefetch = [&](int ck, int stage) {
        int kofs = ck * 32;
        uint32_t se = (uint32_t)stage * STAGE_E;
        #pragma unroll
        for (int i = 0; i < 2; i++) {
            int c = c0 + i;
            int r = c >> 2, seg = c & 3;
            uint32_t dA = sb + 2 * (se + r * TPAD + seg * 8);
            int gr = row0 + r;
            int szA = (gr < Nrows) ? 16 : 0;
            const __nv_bfloat16* pa = Ahi + (size_t)gr * K + kofs + seg * 8;
            const __nv_bfloat16* pl = Alo + (size_t)gr * K + kofs + seg * 8;
            if (szA == 0) { pa = Ahi; pl = Alo; }
            cpa16(dA, pa, szA);
            cpa16(dA + 2 * TILE_E, pl, szA);
            const __nv_bfloat16* pb = BhiT + (size_t)(col0 + r) * K + kofs + seg * 8;
            const __nv_bfloat16* pq = BloT + (size_t)(col0 + r) * K + kofs + seg * 8;
            cpa16(dA + 2 * (2 * TILE_E), pb, 16);
            cpa16(dA + 2 * (3 * TILE_E), pq, 16);
        }
        cpa_commit();
    };

    prefetch(0, 0);

    for (int ck = 0; ck < nk; ck++) {
        int stage = ck & 1;
        if (ck + 1 < nk) { prefetch(ck + 1, stage ^ 1); cpa_wait<1>(); }
        else             { cpa_wait<0>(); }
        __syncthreads();

        uint32_t se = (uint32_t)stage * STAGE_E;
        #pragma unroll
        for (int pass = 0; pass < 3; pass++) {
            uint32_t aoff = se + ((pass == 1) ? TILE_E : 0u);
            uint32_t boff = se + ((pass == 2) ? 3u * TILE_E : 2u * TILE_E);
            #pragma unroll
            for (int ks = 0; ks < 2; ks++) {
                int kw = ks * 16 + csel;
                uint32_t af[4][4];
                #pragma unroll
                for (int mi = 0; mi < 4; mi++)
                    ldsm4(af[mi], sb + 2 * (aoff + (uint32_t)(mBase + mi * 16 + rsel) * TPAD + kw));
                uint32_t bfr[2][4];
                #pragma unroll
                for (int p = 0; p < 2; p++)
                    ldsm4(bfr[p], sb + 2 * (boff + (uint32_t)(nBase + p * 16 + rsel) * TPAD + kw));
                #pragma unroll
                for (int mi = 0; mi < 4; mi++)
                    #pragma unroll
                    for (int ni = 0; ni < 4; ni++) {
                        float* d = acc[mi][ni];
                        uint32_t b0 = bfr[ni >> 1][ni & 1];
                        uint32_t b1 = bfr[ni >> 1][2 + (ni & 1)];
                        asm volatile(
                            "mma.sync.aligned.m16n8k16.row.col.f32.bf16.bf16.f32 "
                            "{%0,%1,%2,%3}, {%4,%5,%6,%7}, {%8,%9}, {%0,%1,%2,%3};"
                            : "+f"(d[0]), "+f"(d[1]), "+f"(d[2]), "+f"(d[3])
                            : "r"(af[mi][0]), "r"(af[mi][1]), "r"(af[mi][2]), "r"(af[mi][3]),
                              "r"(b0), "r"(b1));
                    }
            }
        }
        __syncthreads();
    }

    #pragma unroll
    for (int mi = 0; mi < 4; mi++) {
        int r0 = row0 + mBase + mi * 16 + g;
        #pragma unroll
        for (int ni = 0; ni < 4; ni++) {
            int cc = col0 + nBase + ni * 8 + cw * 2;
            if (r0 < Nrows)
                *(float2*)(C + (size_t)r0 * M + cc) = make_float2(acc[mi][ni][0], acc[mi][ni][1]);
            if (r0 + 8 < Nrows)
                *(float2*)(C + (size_t)(r0 + 8) * M + cc) = make_float2(acc[mi][ni][2], acc[mi][ni][3]);
        }
    }
}

// ---------------- fused GATv2 edge kernel: one warp per dst -----------------
__global__ __launch_bounds__(256) void k_gat_edge(const float* __restrict__ att,
                                                  const float* __restrict__ bias) {
    int gw = (blockIdx.x * 256 + threadIdx.x) >> 5;
    int lane = threadIdx.x & 31;
    if (gw >= NN) return;
    int d = gw;
    int rs = g_rs[d], re = g_rs[d + 1];

    float4 xr4[4], at4[4];
    const float4* pxr = (const float4*)(g_xlr + (size_t)d * 1024 + 512);
    const float4* pat = (const float4*)att;
    #pragma unroll
    for (int j = 0; j < 4; j++) {
        xr4[j] = pxr[j * 32 + lane];
        at4[j] = pat[j * 32 + lane];
    }

    float m = -3.0e38f;
    for (int e = rs; e < re; e++) {
        int s = g_csrc[e];
        const float4* pxl = (const float4*)(g_xlr + (size_t)s * 1024);
        float acc = 0.f;
        #pragma unroll
        for (int j = 0; j < 4; j++) {
            float4 a = pxl[j * 32 + lane];
            float v;
            v = a.x + xr4[j].x; v = v > 0.f ? v : 0.2f * v; acc += v * at4[j].x;
            v = a.y + xr4[j].y; v = v > 0.f ? v : 0.2f * v; acc += v * at4[j].y;
            v = a.z + xr4[j].z; v = v > 0.f ? v : 0.2f * v; acc += v * at4[j].z;
            v = a.w + xr4[j].w; v = v > 0.f ? v : 0.2f * v; acc += v * at4[j].w;
        }
        #pragma unroll
        for (int o = 16; o; o >>= 1) acc += __shfl_xor_sync(0xffffffffu, acc, o);
        if (lane == 0) g_e[e] = acc;
        m = fmaxf(m, acc);
    }

    float den = 0.f;
    float accf[16];
    #pragma unroll
    for (int j = 0; j < 16; j++) accf[j] = 0.f;

    for (int e = rs; e < re; e++) {
        int s = g_csrc[e];
        float w = expf(g_e[e] - m);
        den += w;
        const float4* pxl = (const float4*)(g_xlr + (size_t)s * 1024);
        #pragma unroll
        for (int j = 0; j < 4; j++) {
            float4 a = pxl[j * 32 + lane];
            accf[4 * j + 0] += w * a.x;
            accf[4 * j + 1] += w * a.y;
            accf[4 * j + 2] += w * a.z;
            accf[4 * j + 3] += w * a.w;
        }
    }

    float inv = 1.0f / (den + 1e-16f);
    const float4* pb = (const float4*)bias;
    __nv_bfloat16* ph = g_ahi + (size_t)d * DE;
    __nv_bfloat16* pl = g_alo + (size_t)d * DE;
    #pragma unroll
    for (int j = 0; j < 4; j++) {
        float4 b = pb[j * 32 + lane];
        float t0 = tanhf(accf[4 * j + 0] * inv + b.x);
        float t1 = tanhf(accf[4 * j + 1] * inv + b.y);
        float t2 = tanhf(accf[4 * j + 2] * inv + b.z);
        float t3 = tanhf(accf[4 * j + 3] * inv + b.w);
        __nv_bfloat162 h01 = __floats2bfloat162_rn(t0, t1);
        __nv_bfloat162 h23 = __floats2bfloat162_rn(t2, t3);
        float l0 = t0 - __bfloat162float(__low2bfloat16(h01));
        float l1 = t1 - __bfloat162float(__high2bfloat16(h01));
        float l2 = t2 - __bfloat162float(__low2bfloat16(h23));
        float l3 = t3 - __bfloat162float(__high2bfloat16(h23));
        __nv_bfloat162 q01 = __floats2bfloat162_rn(l0, l1);
        __nv_bfloat162 q23 = __floats2bfloat162_rn(l2, l3);
        uint2 uh, ul;
        uh.x = *(uint32_t*)&h01; uh.y = *(uint32_t*)&h23;
        ul.x = *(uint32_t*)&q01; ul.y = *(uint32_t*)&q23;
        ((uint2*)ph)[j * 32 + lane] = uh;
        ((uint2*)pl)[j * 32 + lane] = ul;
    }
}

// ---------------- MLP kernels ----------------------------------------------
__global__ void k_blsplit(float* __restrict__ p, const float* __restrict__ c,
                          __nv_bfloat16* __restrict__ hi, __nv_bfloat16* __restrict__ lo,
                          int dim, int n) {
    int i = blockIdx.x * blockDim.x + threadIdx.x;
    if (i >= n) return;
    float v = p[i] + c[i % dim];
    v = (v > 0.f) ? v : 0.1f * v;
    p[i] = v;
    __nv_bfloat16 h = __float2bfloat16_rn(v);
    hi[i] = h;
    lo[i] = __float2bfloat16_rn(v - __bfloat162float(h));
}

__global__ void k_dot3(const float* __restrict__ A3, const float* __restrict__ c3) {
    int gt = blockIdx.x * blockDim.x + threadIdx.x;
    int n = gt >> 5;
    int lane = gt & 31;
    if (n >= NN) return;
    const float4* pm = (const float4*)(g_m2 + (size_t)n * DH);
    const float4* pw = (const float4*)A3;
    float acc = 0.f;
    #pragma unroll
    for (int i = 0; i < DH / 128; i++) {
        int k = i * 32 + lane;
        float4 m = pm[k], w = pw[k];
        acc += m.x * w.x + m.y * w.y + m.z * w.z + m.w * w.w;
    }
    #pragma unroll
    for (int o = 16; o; o >>= 1) acc += __shfl_xor_sync(0xffffffffu, acc, o);
    if (lane == 0) g_logit[n] = acc + c3[0];
}

__global__ void k_softmax(float* __restrict__ out) {
    __shared__ float sh[1024];
    int t = threadIdx.x;
    float m = -3.0e38f;
    for (int i = t; i < NN; i += 1024) m = fmaxf(m, g_logit[i]);
    sh[t] = m; __syncthreads();
    for (int s = 512; s; s >>= 1) { if (t < s) sh[t] = fmaxf(sh[t], sh[t + s]); __syncthreads(); }
    float gm = sh[0]; __syncthreads();
    float sum = 0.f;
    for (int i = t; i < NN; i += 1024) sum += expf(g_logit[i] - gm);
    sh[t] = sum; __syncthreads();
    for (int s = 512; s; s >>= 1) { if (t < s) sh[t] += sh[t + s]; __syncthreads(); }
    float gs = sh[0];
    for (int i = t; i < NN; i += 1024) out[i] = expf(g_logit[i] - gm) / gs;
}

// ---------------- host side -------------------------------------------------
static __nv_bfloat16 *s_ahi, *s_alo, *s_whi, *s_wlo;

static void run_gemm(int K, int M, float* Cout) {
    dim3 g(M / 128, (NN + 127) / 128);
    k_gemm_mma<<<g, 256, SMEM_GEMM>>>(s_ahi, s_alo, s_whi, s_wlo, Cout, NN, K, M);
}

static void gat_layer(int din, const float* Wl, const float* Wr,
                      const float* att, const float* bias, float* xlr) {
    k_prep_w<<<(din * DE + 255) / 256, 256>>>(Wl, s_whi, s_wlo, din, DE, 0);
    k_prep_w<<<(din * DE + 255) / 256, 256>>>(Wr, s_whi, s_wlo, din, DE, DE);
    run_gemm(din, 2 * DE, xlr);
    k_gat_edge<<<(NN * 32 + 255) / 256, 256>>>(att, bias);
}

extern "C" void kernel_launch(void* const* d_in, const int* in_sizes, int n_in,
                              void* d_out, int out_size) {
    const float* x   = (const float*)d_in[0];
    const int*   ei  = (const int*)d_in[1];
    const float* Wl1 = (const float*)d_in[2];
    const float* Wr1 = (const float*)d_in[3];
    const float* at1 = (const float*)d_in[4];
    const float* b1  = (const float*)d_in[5];
    const float* Wl2 = (const float*)d_in[6];
    const float* Wr2 = (const float*)d_in[7];
    const float* at2 = (const float*)d_in[8];
    const float* b2  = (const float*)d_in[9];
    const float* Wl3 = (const float*)d_in[10];
    const float* Wr3 = (const float*)d_in[11];
    const float* at3 = (const float*)d_in[12];
    const float* b3  = (const float*)d_in[13];
    const float* A1  = (const float*)d_in[14];
    const float* c1  = (const float*)d_in[15];
    const float* A2  = (const float*)d_in[16];
    const float* c2  = (const float*)d_in[17];
    const float* A3  = (const float*)d_in[18];
    const float* c3  = (const float*)d_in[19];
    float* out = (float*)d_out;

    cudaFuncSetAttribute(k_gemm_mma, cudaFuncAttributeMaxDynamicSharedMemorySize, SMEM_GEMM);

    float *xlr, *m1, *m2;
    cudaGetSymbolAddress((void**)&xlr, g_xlr);
    cudaGetSymbolAddress((void**)&m1,  g_m1);
    cudaGetSymbolAddress((void**)&m2,  g_m2);
    cudaGetSymbolAddress((void**)&s_ahi, g_ahi);
    cudaGetSymbolAddress((void**)&s_alo, g_alo);
    cudaGetSymbolAddress((void**)&s_whi, g_whi);
    cudaGetSymbolAddress((void**)&s_wlo, g_wlo);

    // edges + CSR by dst
    k_detect<<<1, 256>>>(ei);
    k_edges<<<(NE + 255) / 256, 256>>>(ei);
    k_zero_deg<<<(NN + 255) / 256, 256>>>();
    k_hist<<<(NE + 255) / 256, 256>>>();
    k_scan<<<1, 1024>>>();
    k_setcur<<<(NN + 255) / 256, 256>>>();
    k_scatter<<<(NE + 255) / 256, 256>>>();

    // layer 1 input split
    k_split<<<(NN * DI + 255) / 256, 256>>>(x, s_ahi, s_alo, NN * DI);

    gat_layer(DI, Wl1, Wr1, at1, b1, xlr);
    gat_layer(DE, Wl2, Wr2, at2, b2, xlr);
    gat_layer(DE, Wl3, Wr3, at3, b3, xlr);

    // MLP (consumes s_ahi/s_alo holding layer-3 output)
    k_prep_w<<<(DE * DH + 255) / 256, 256>>>(A1, s_whi, s_wlo, DE, DH, 0);
    run_gemm(DE, DH, m1);
    k_blsplit<<<(NN * DH + 255) / 256, 256>>>(m1, c1, s_ahi, s_alo, DH, NN * DH);
    k_prep_w<<<(DH * DH + 255) / 256, 256>>>(A2, s_whi, s_wlo, DH, DH, 0);
    run_gemm(DH, DH, m2);
    k_blsplit<<<(NN * DH + 255) / 256, 256>>>(m2, c2, s_ahi, s_alo, DH, NN * DH);
    k_dot3<<<(NN * 32 + 255) / 256, 256>>>(A3, c3);
    k_softmax<<<1, 1024>>>(out);
}

// round 8
// speedup vs baseline: 1.9997x; 1.0597x over previous
#include <cuda_runtime.h>
#include <cuda_bf16.h>
#include <math.h>
#include <stdint.h>

#define NN 10000
#define NE 160000
#define DI 128
#define DE 512
#define DH 256

// ---------------- scratch (device globals; no allocation allowed) ----------
__device__ __align__(16) float g_xlr[NN * 2 * DE];   // [node][xl(512) | xr(512)]
__device__ float g_e[NE];
__device__ int   g_src[NE];
__device__ int   g_dst[NE];
__device__ int   g_deg[NN];
__device__ int   g_rs[NN + 1];
__device__ int   g_cur[NN];
__device__ int   g_csrc[NE];
__device__ __align__(16) float g_m1[NN * DH];
__device__ __align__(16) float g_m2[NN * DH];
__device__ float g_logit[NN];
__device__ int   g_is64;
__device__ __align__(16) __nv_bfloat16 g_ahi[NN * DE];
__device__ __align__(16) __nv_bfloat16 g_alo[NN * DE];
__device__ __align__(16) __nv_bfloat16 g_whi[2 * DE * DE];
__device__ __align__(16) __nv_bfloat16 g_wlo[2 * DE * DE];

// ---------------- edge decode + CSR build ----------------------------------
__global__ void k_detect(const int* __restrict__ w) {
    __shared__ int s;
    if (threadIdx.x == 0) s = 0;
    __syncthreads();
    int acc = 0;
    for (int i = threadIdx.x; i < 2048; i += 256) acc |= w[2 * i + 1];
    atomicOr(&s, acc);
    // fold in deg zeroing (single-block kernel, spare bandwidth)
    for (int i = threadIdx.x; i < NN; i += 256) g_deg[i] = 0;
    __syncthreads();
    if (threadIdx.x == 0) g_is64 = (s == 0) ? 1 : 0;
}

__global__ void k_edges(const int* __restrict__ w) {
    int i = blockIdx.x * blockDim.x + threadIdx.x;
    if (i >= NE) return;
    int s, d;
    if (g_is64) { s = w[2 * i]; d = w[2 * (NE + i)]; }
    else        { s = w[i];     d = w[NE + i]; }
    if ((unsigned)s >= NN) s = 0;
    if ((unsigned)d >= NN) d = 0;
    g_src[i] = s;
    g_dst[i] = d;
}

__global__ void k_hist() {
    int i = blockIdx.x * blockDim.x + threadIdx.x;
    if (i < NE) atomicAdd(&g_deg[g_dst[i]], 1);
}

__global__ void k_scan() {
    __shared__ int s[1024];
    __shared__ int sbase;
    int t = threadIdx.x;
    if (t == 0) sbase = 0;
    __syncthreads();
    for (int chunk = 0; chunk < NN; chunk += 1024) {
        int idx = chunk + t;
        int v = (idx < NN) ? g_deg[idx] : 0;
        s[t] = v;
        __syncthreads();
        for (int off = 1; off < 1024; off <<= 1) {
            int u = (t >= off) ? s[t - off] : 0;
            __syncthreads();
            s[t] += u;
            __syncthreads();
        }
        if (idx < NN) { int r = sbase + s[t] - v; g_rs[idx] = r; g_cur[idx] = r; }
        int tot = s[1023];
        __syncthreads();
        if (t == 0) sbase += tot;
        __syncthreads();
    }
    if (t == 0) g_rs[NN] = sbase;
}

__global__ void k_scatter() {
    int i = blockIdx.x * blockDim.x + threadIdx.x;
    if (i >= NE) return;
    int pos = atomicAdd(&g_cur[g_dst[i]], 1);
    g_csrc[pos] = g_src[i];
}

// ---------------- hi/lo split (layer-1 input only) ---------------------------
__global__ void k_split(const float* __restrict__ a, __nv_bfloat16* __restrict__ hi,
                        __nv_bfloat16* __restrict__ lo, int n) {
    int i = blockIdx.x * blockDim.x + threadIdx.x;
    if (i >= n) return;
    float v = a[i];
    __nv_bfloat16 h = __float2bfloat16_rn(v);
    hi[i] = h;
    lo[i] = __float2bfloat16_rn(v - __bfloat162float(h));
}

// ---------------- coalesced weight prep: W[K,M] -> WT[m+rofs][K] hi/lo -------
// tile: 64 (k) x 32 (m); smem transpose; bf162-paired coalesced writes.
__global__ __launch_bounds__(256) void k_prep_w(
    const float* __restrict__ W, __nv_bfloat16* __restrict__ hiT,
    __nv_bfloat16* __restrict__ loT, int K, int M, int rofs) {
    __shared__ float s[64][33];
    int k0 = blockIdx.x * 64, m0 = blockIdx.y * 32;
    int tid = threadIdx.x;
    #pragma unroll
    for (int i = tid; i < 64 * 32; i += 256) {
        int kk = i >> 5, mm = i & 31;
        s[kk][mm] = W[(size_t)(k0 + kk) * M + m0 + mm];
    }
    __syncthreads();
    #pragma unroll
    for (int i = tid; i < 32 * 32; i += 256) {
        int mm = i >> 5, kp = i & 31;
        float v0 = s[2 * kp][mm], v1 = s[2 * kp + 1][mm];
        __nv_bfloat162 h2 = __floats2bfloat162_rn(v0, v1);
        float l0 = v0 - __bfloat162float(__low2bfloat16(h2));
        float l1 = v1 - __bfloat162float(__high2bfloat16(h2));
        __nv_bfloat162 l2 = __floats2bfloat162_rn(l0, l1);
        size_t ro = (size_t)(m0 + mm + rofs) * K + k0 + 2 * kp;
        *(uint32_t*)(hiT + ro) = *(uint32_t*)&h2;
        *(uint32_t*)(loT + ro) = *(uint32_t*)&l2;
    }
}

// ---------------- cp.async + ldmatrix bf16 GEMM (3-pass hi/lo) --------------
#define TPAD 40
#define TILE_E (128 * TPAD)
#define STAGE_E (4 * TILE_E)
#define SMEM_GEMM (2 * STAGE_E * 2)

__device__ __forceinline__ void cpa16(uint32_t dst, const void* src, int sz) {
    asm volatile("cp.async.cg.shared.global [%0], [%1], 16, %2;"
                 :: "r"(dst), "l"(src), "r"(sz) : "memory");
}
__device__ __forceinline__ void cpa_commit() {
    asm volatile("cp.async.commit_group;" ::: "memory");
}
template<int N> __device__ __forceinline__ void cpa_wait() {
    asm volatile("cp.async.wait_group %0;" :: "n"(N) : "memory");
}
__device__ __forceinline__ void ldsm4(uint32_t* r, uint32_t addr) {
    asm volatile("ldmatrix.sync.aligned.m8n8.x4.shared.b16 {%0,%1,%2,%3}, [%4];"
                 : "=r"(r[0]), "=r"(r[1]), "=r"(r[2]), "=r"(r[3]) : "r"(addr));
}

// mode bit0: bias + leaky(0.1); mode bit1: also write bf16 hi/lo to Hi/Lo[r*M+c]
__global__ __launch_bounds__(256) void k_gemm_mma(
    const __nv_bfloat16* __restrict__ Ahi, const __nv_bfloat16* __restrict__ Alo,
    const __nv_bfloat16* __restrict__ BhiT, const __nv_bfloat16* __restrict__ BloT,
    float* __restrict__ C, int Nrows, int K, int M,
    const float* __restrict__ bias, int mode,
    __nv_bfloat16* __restrict__ Hi, __nv_bfloat16* __restrict__ Lo)
{
    extern __shared__ __nv_bfloat16 smem[];
    uint32_t sb = (uint32_t)__cvta_generic_to_shared(smem);

    int tid = threadIdx.x;
    int wid = tid >> 5, lane = tid & 31;
    int wm = wid & 1, wn = wid >> 1;
    int row0 = blockIdx.y * 128;
    int col0 = blockIdx.x * 128;
    int mBase = wm * 64, nBase = wn * 32;
    int g = lane >> 2, cw = lane & 3;
    int mat = lane >> 3, r8 = lane & 7;
    int rsel = (mat & 1) * 8 + r8;
    int csel = (mat >> 1) * 8;

    float acc[4][4][4];
    #pragma unroll
    for (int a = 0; a < 4; a++)
        #pragma unroll
        for (int b = 0; b < 4; b++)
            #pragma unroll
            for (int c = 0; c < 4; c++) acc[a][b][c] = 0.f;

    int nk = K / 32;
    int c0 = tid * 2;

    auto prefetch = [&](int ck, int stage) {
        int kofs = ck * 32;
        uint32_t se = (uint32_t)stage * STAGE_E;
        #pragma unroll
        for (int i = 0; i < 2; i++) {
            int c = c0 + i;
            int r = c >> 2, seg = c & 3;
            uint32_t dA = sb + 2 * (se + r * TPAD + seg * 8);
            int gr = row0 + r;
            int szA = (gr < Nrows) ? 16 : 0;
            const __nv_bfloat16* pa = Ahi + (size_t)gr * K + kofs + seg * 8;
            const __nv_bfloat16* pl = Alo + (size_t)gr * K + kofs + seg * 8;
            if (szA == 0) { pa = Ahi; pl = Alo; }
            cpa16(dA, pa, szA);
            cpa16(dA + 2 * TILE_E, pl, szA);
            const __nv_bfloat16* pb = BhiT + (size_t)(col0 + r) * K + kofs + seg * 8;
            const __nv_bfloat16* pq = BloT + (size_t)(col0 + r) * K + kofs + seg * 8;
            cpa16(dA + 2 * (2 * TILE_E), pb, 16);
            cpa16(dA + 2 * (3 * TILE_E), pq, 16);
        }
        cpa_commit();
    };

    prefetch(0, 0);

    for (int ck = 0; ck < nk; ck++) {
        int stage = ck & 1;
        if (ck + 1 < nk) { prefetch(ck + 1, stage ^ 1); cpa_wait<1>(); }
        else             { cpa_wait<0>(); }
        __syncthreads();

        uint32_t se = (uint32_t)stage * STAGE_E;
        #pragma unroll
        for (int pass = 0; pass < 3; pass++) {
            uint32_t aoff = se + ((pass == 1) ? TILE_E : 0u);
            uint32_t boff = se + ((pass == 2) ? 3u * TILE_E : 2u * TILE_E);
            #pragma unroll
            for (int ks = 0; ks < 2; ks++) {
                int kw = ks * 16 + csel;
                uint32_t af[4][4];
                #pragma unroll
                for (int mi = 0; mi < 4; mi++)
                    ldsm4(af[mi], sb + 2 * (aoff + (uint32_t)(mBase + mi * 16 + rsel) * TPAD + kw));
                uint32_t bfr[2][4];
                #pragma unroll
                for (int p = 0; p < 2; p++)
                    ldsm4(bfr[p], sb + 2 * (boff + (uint32_t)(nBase + p * 16 + rsel) * TPAD + kw));
                #pragma unroll
                for (int mi = 0; mi < 4; mi++)
                    #pragma unroll
                    for (int ni = 0; ni < 4; ni++) {
                        float* d = acc[mi][ni];
                        uint32_t b0 = bfr[ni >> 1][ni & 1];
                        uint32_t b1 = bfr[ni >> 1][2 + (ni & 1)];
                        asm volatile(
                            "mma.sync.aligned.m16n8k16.row.col.f32.bf16.bf16.f32 "
                            "{%0,%1,%2,%3}, {%4,%5,%6,%7}, {%8,%9}, {%0,%1,%2,%3};"
                            : "+f"(d[0]), "+f"(d[1]), "+f"(d[2]), "+f"(d[3])
                            : "r"(af[mi][0]), "r"(af[mi][1]), "r"(af[mi][2]), "r"(af[mi][3]),
                              "r"(b0), "r"(b1));
                    }
            }
        }
        __syncthreads();
    }

    #pragma unroll
    for (int mi = 0; mi < 4; mi++) {
        int r0 = row0 + mBase + mi * 16 + g;
        #pragma unroll
        for (int ni = 0; ni < 4; ni++) {
            int cc = col0 + nBase + ni * 8 + cw * 2;
            float v0 = acc[mi][ni][0], v1 = acc[mi][ni][1];
            float v2 = acc[mi][ni][2], v3 = acc[mi][ni][3];
            if (mode & 1) {
                float b0 = bias[cc], b1 = bias[cc + 1];
                v0 += b0; v0 = (v0 > 0.f) ? v0 : 0.1f * v0;
                v1 += b1; v1 = (v1 > 0.f) ? v1 : 0.1f * v1;
                v2 += b0; v2 = (v2 > 0.f) ? v2 : 0.1f * v2;
                v3 += b1; v3 = (v3 > 0.f) ? v3 : 0.1f * v3;
            }
            if (r0 < Nrows) {
                *(float2*)(C + (size_t)r0 * M + cc) = make_float2(v0, v1);
                if (mode & 2) {
                    __nv_bfloat162 h2 = __floats2bfloat162_rn(v0, v1);
                    float l0 = v0 - __bfloat162float(__low2bfloat16(h2));
                    float l1 = v1 - __bfloat162float(__high2bfloat16(h2));
                    __nv_bfloat162 l2 = __floats2bfloat162_rn(l0, l1);
                    *(uint32_t*)(Hi + (size_t)r0 * M + cc) = *(uint32_t*)&h2;
                    *(uint32_t*)(Lo + (size_t)r0 * M + cc) = *(uint32_t*)&l2;
                }
            }
            if (r0 + 8 < Nrows) {
                *(float2*)(C + (size_t)(r0 + 8) * M + cc) = make_float2(v2, v3);
                if (mode & 2) {
                    __nv_bfloat162 h2 = __floats2bfloat162_rn(v2, v3);
                    float l0 = v2 - __bfloat162float(__low2bfloat16(h2));
                    float l1 = v3 - __bfloat162float(__high2bfloat16(h2));
                    __nv_bfloat162 l2 = __floats2bfloat162_rn(l0, l1);
                    *(uint32_t*)(Hi + (size_t)(r0 + 8) * M + cc) = *(uint32_t*)&h2;
                    *(uint32_t*)(Lo + (size_t)(r0 + 8) * M + cc) = *(uint32_t*)&l2;
                }
            }
        }
    }
}

// ---------------- fused GATv2 edge kernel: one warp per dst -----------------
__global__ __launch_bounds__(256) void k_gat_edge(const float* __restrict__ att,
                                                  const float* __restrict__ bias) {
    int gw = (blockIdx.x * 256 + threadIdx.x) >> 5;
    int lane = threadIdx.x & 31;
    if (gw >= NN) return;
    int d = gw;
    int rs = g_rs[d], re = g_rs[d + 1];

    float4 xr4[4], at4[4];
    const float4* pxr = (const float4*)(g_xlr + (size_t)d * 1024 + 512);
    const float4* pat = (const float4*)att;
    #pragma unroll
    for (int j = 0; j < 4; j++) {
        xr4[j] = pxr[j * 32 + lane];
        at4[j] = pat[j * 32 + lane];
    }

    float m = -3.0e38f;
    for (int e = rs; e < re; e++) {
        int s = g_csrc[e];
        const float4* pxl = (const float4*)(g_xlr + (size_t)s * 1024);
        float acc = 0.f;
        #pragma unroll
        for (int j = 0; j < 4; j++) {
            float4 a = pxl[j * 32 + lane];
            float v;
            v = a.x + xr4[j].x; v = v > 0.f ? v : 0.2f * v; acc += v * at4[j].x;
            v = a.y + xr4[j].y; v = v > 0.f ? v : 0.2f * v; acc += v * at4[j].y;
            v = a.z + xr4[j].z; v = v > 0.f ? v : 0.2f * v; acc += v * at4[j].z;
            v = a.w + xr4[j].w; v = v > 0.f ? v : 0.2f * v; acc += v * at4[j].w;
        }
        #pragma unroll
        for (int o = 16; o; o >>= 1) acc += __shfl_xor_sync(0xffffffffu, acc, o);
        if (lane == 0) g_e[e] = acc;
        m = fmaxf(m, acc);
    }

    float den = 0.f;
    float accf[16];
    #pragma unroll
    for (int j = 0; j < 16; j++) accf[j] = 0.f;

    for (int e = rs; e < re; e++) {
        int s = g_csrc[e];
        float w = expf(g_e[e] - m);
        den += w;
        const float4* pxl = (const float4*)(g_xlr + (size_t)s * 1024);
        #pragma unroll
        for (int j = 0; j < 4; j++) {
            float4 a = pxl[j * 32 + lane];
            accf[4 * j + 0] += w * a.x;
            accf[4 * j + 1] += w * a.y;
            accf[4 * j + 2] += w * a.z;
            accf[4 * j + 3] += w * a.w;
        }
    }

    float inv = 1.0f / (den + 1e-16f);
    const float4* pb = (const float4*)bias;
    __nv_bfloat16* ph = g_ahi + (size_t)d * DE;
    __nv_bfloat16* pl = g_alo + (size_t)d * DE;
    #pragma unroll
    for (int j = 0; j < 4; j++) {
        float4 b = pb[j * 32 + lane];
        float t0 = tanhf(accf[4 * j + 0] * inv + b.x);
        float t1 = tanhf(accf[4 * j + 1] * inv + b.y);
        float t2 = tanhf(accf[4 * j + 2] * inv + b.z);
        float t3 = tanhf(accf[4 * j + 3] * inv + b.w);
        __nv_bfloat162 h01 = __floats2bfloat162_rn(t0, t1);
        __nv_bfloat162 h23 = __floats2bfloat162_rn(t2, t3);
        float l0 = t0 - __bfloat162float(__low2bfloat16(h01));
        float l1 = t1 - __bfloat162float(__high2bfloat16(h01));
        float l2 = t2 - __bfloat162float(__low2bfloat16(h23));
        float l3 = t3 - __bfloat162float(__high2bfloat16(h23));
        __nv_bfloat162 q01 = __floats2bfloat162_rn(l0, l1);
        __nv_bfloat162 q23 = __floats2bfloat162_rn(l2, l3);
        uint2 uh, ul;
        uh.x = *(uint32_t*)&h01; uh.y = *(uint32_t*)&h23;
        ul.x = *(uint32_t*)&q01; ul.y = *(uint32_t*)&q23;
        ((uint2*)ph)[j * 32 + lane] = uh;
        ((uint2*)pl)[j * 32 + lane] = ul;
    }
}

// ---------------- final MLP tail --------------------------------------------
__global__ void k_dot3(const float* __restrict__ A3, const float* __restrict__ c3) {
    int gt = blockIdx.x * blockDim.x + threadIdx.x;
    int n = gt >> 5;
    int lane = gt & 31;
    if (n >= NN) return;
    const float4* pm = (const float4*)(g_m2 + (size_t)n * DH);
    const float4* pw = (const float4*)A3;
    float acc = 0.f;
    #pragma unroll
    for (int i = 0; i < DH / 128; i++) {
        int k = i * 32 + lane;
        float4 m = pm[k], w = pw[k];
        acc += m.x * w.x + m.y * w.y + m.z * w.z + m.w * w.w;
    }
    #pragma unroll
    for (int o = 16; o; o >>= 1) acc += __shfl_xor_sync(0xffffffffu, acc, o);
    if (lane == 0) g_logit[n] = acc + c3[0];
}

__global__ void k_softmax(float* __restrict__ out) {
    __shared__ float sh[1024];
    int t = threadIdx.x;
    float m = -3.0e38f;
    for (int i = t; i < NN; i += 1024) m = fmaxf(m, g_logit[i]);
    sh[t] = m; __syncthreads();
    for (int s = 512; s; s >>= 1) { if (t < s) sh[t] = fmaxf(sh[t], sh[t + s]); __syncthreads(); }
    float gm = sh[0]; __syncthreads();
    float sum = 0.f;
    for (int i = t; i < NN; i += 1024) sum += expf(g_logit[i] - gm);
    sh[t] = sum; __syncthreads();
    for (int s = 512; s; s >>= 1) { if (t < s) sh[t] += sh[t + s]; __syncthreads(); }
    float gs = sh[0];
    for (int i = t; i < NN; i += 1024) out[i] = expf(g_logit[i] - gm) / gs;
}

// ---------------- host side -------------------------------------------------
static __nv_bfloat16 *s_ahi, *s_alo, *s_whi, *s_wlo;

static void run_gemm(int K, int M, float* Cout, const float* bias, int mode) {
    dim3 g(M / 128, (NN + 127) / 128);
    k_gemm_mma<<<g, 256, SMEM_GEMM>>>(s_ahi, s_alo, s_whi, s_wlo, Cout, NN, K, M,
                                      bias, mode, s_ahi, s_alo);
}

static void prep_w(const float* W, int K, int M, int rofs) {
    dim3 g(K / 64, M / 32);
    k_prep_w<<<g, 256>>>(W, s_whi, s_wlo, K, M, rofs);
}

static void gat_layer(int din, const float* Wl, const float* Wr,
                      const float* att, const float* bias, float* xlr) {
    prep_w(Wl, din, DE, 0);
    prep_w(Wr, din, DE, DE);
    run_gemm(din, 2 * DE, xlr, nullptr, 0);
    k_gat_edge<<<(NN * 32 + 255) / 256, 256>>>(att, bias);
}

extern "C" void kernel_launch(void* const* d_in, const int* in_sizes, int n_in,
                              void* d_out, int out_size) {
    const float* x   = (const float*)d_in[0];
    const int*   ei  = (const int*)d_in[1];
    const float* Wl1 = (const float*)d_in[2];
    const float* Wr1 = (const float*)d_in[3];
    const float* at1 = (const float*)d_in[4];
    const float* b1  = (const float*)d_in[5];
    const float* Wl2 = (const float*)d_in[6];
    const float* Wr2 = (const float*)d_in[7];
    const float* at2 = (const float*)d_in[8];
    const float* b2  = (const float*)d_in[9];
    const float* Wl3 = (const float*)d_in[10];
    const float* Wr3 = (const float*)d_in[11];
    const float* at3 = (const float*)d_in[12];
    const float* b3  = (const float*)d_in[13];
    const float* A1  = (const float*)d_in[14];
    const float* c1  = (const float*)d_in[15];
    const float* A2  = (const float*)d_in[16];
    const float* c2  = (const float*)d_in[17];
    const float* A3  = (const float*)d_in[18];
    const float* c3  = (const float*)d_in[19];
    float* out = (float*)d_out;

    cudaFuncSetAttribute(k_gemm_mma, cudaFuncAttributeMaxDynamicSharedMemorySize, SMEM_GEMM);

    float *xlr, *m1, *m2;
    cudaGetSymbolAddress((void**)&xlr, g_xlr);
    cudaGetSymbolAddress((void**)&m1,  g_m1);
    cudaGetSymbolAddress((void**)&m2,  g_m2);
    cudaGetSymbolAddress((void**)&s_ahi, g_ahi);
    cudaGetSymbolAddress((void**)&s_alo, g_alo);
    cudaGetSymbolAddress((void**)&s_whi, g_whi);
    cudaGetSymbolAddress((void**)&s_wlo, g_wlo);

    // edges + CSR by dst (5 launches)
    k_detect<<<1, 256>>>(ei);
    k_edges<<<(NE + 255) / 256, 256>>>(ei);
    k_hist<<<(NE + 255) / 256, 256>>>();
    k_scan<<<1, 1024>>>();
    k_scatter<<<(NE + 255) / 256, 256>>>();

    // layer 1 input split
    k_split<<<(NN * DI + 255) / 256, 256>>>(x, s_ahi, s_alo, NN * DI);

    gat_layer(DI, Wl1, Wr1, at1, b1, xlr);
    gat_layer(DE, Wl2, Wr2, at2, b2, xlr);
    gat_layer(DE, Wl3, Wr3, at3, b3, xlr);

    // MLP: gemm epilogue fuses bias+leaky (+hi/lo split for the next gemm)
    prep_w(A1, DE, DH, 0);
    run_gemm(DE, DH, m1, c1, 3);
    prep_w(A2, DH, DH, 0);
    run_gemm(DH, DH, m2, c2, 1);
    k_dot3<<<(NN * 32 + 255) / 256, 256>>>(A3, c3);
    k_softmax<<<1, 1024>>>(out);
}

// round 9
// speedup vs baseline: 2.1235x; 1.0619x over previous
#include <cuda_runtime.h>
#include <cuda_bf16.h>
#include <math.h>
#include <stdint.h>

#define NN 10000
#define NE 160000
#define DI 128
#define DE 512
#define DH 256

// ---------------- scratch (device globals; no allocation allowed) ----------
__device__ __align__(16) float g_xlr[NN * 2 * DE];   // [node][xl(512) | xr(512)]
__device__ int   g_src[NE];
__device__ int   g_dst[NE];
__device__ int   g_deg[NN];
__device__ int   g_rs[NN + 1];
__device__ int   g_cur[NN];
__device__ int   g_csrc[NE];
__device__ __align__(16) float g_m1[NN * DH];
__device__ __align__(16) float g_m2[NN * DH];
__device__ float g_logit[NN];
__device__ int   g_is64;
__device__ __align__(16) __nv_bfloat16 g_ahi[NN * DE];
__device__ __align__(16) __nv_bfloat16 g_alo[NN * DE];
__device__ __align__(16) __nv_bfloat16 g_whi[2 * DE * DE];
__device__ __align__(16) __nv_bfloat16 g_wlo[2 * DE * DE];

// ---------------- edge decode + CSR build ----------------------------------
__global__ void k_detect(const int* __restrict__ w) {
    __shared__ int s;
    if (threadIdx.x == 0) s = 0;
    __syncthreads();
    int acc = 0;
    for (int i = threadIdx.x; i < 2048; i += 256) acc |= w[2 * i + 1];
    atomicOr(&s, acc);
    for (int i = threadIdx.x; i < NN; i += 256) g_deg[i] = 0;
    __syncthreads();
    if (threadIdx.x == 0) g_is64 = (s == 0) ? 1 : 0;
}

__global__ void k_edges(const int* __restrict__ w) {
    int i = blockIdx.x * blockDim.x + threadIdx.x;
    if (i >= NE) return;
    int s, d;
    if (g_is64) { s = w[2 * i]; d = w[2 * (NE + i)]; }
    else        { s = w[i];     d = w[NE + i]; }
    if ((unsigned)s >= NN) s = 0;
    if ((unsigned)d >= NN) d = 0;
    g_src[i] = s;
    g_dst[i] = d;
}

__global__ void k_hist() {
    int i = blockIdx.x * blockDim.x + threadIdx.x;
    if (i < NE) atomicAdd(&g_deg[g_dst[i]], 1);
}

// warp-shuffle 3-level scan: 1024 threads x 10 items
__global__ void k_scan() {
    __shared__ int wsum[32];
    int t = threadIdx.x;
    int lane = t & 31, w = t >> 5;
    int base_i = t * 10;
    int loc[10];
    int sum = 0;
    #pragma unroll
    for (int j = 0; j < 10; j++) {
        int idx = base_i + j;
        int v = (idx < NN) ? g_deg[idx] : 0;
        loc[j] = sum; sum += v;
    }
    int inc = sum;
    #pragma unroll
    for (int o = 1; o < 32; o <<= 1) {
        int u = __shfl_up_sync(0xffffffffu, inc, o);
        if (lane >= o) inc += u;
    }
    if (lane == 31) wsum[w] = inc;
    __syncthreads();
    if (w == 0) {
        int v = wsum[lane];
        #pragma unroll
        for (int o = 1; o < 32; o <<= 1) {
            int u = __shfl_up_sync(0xffffffffu, v, o);
            if (lane >= o) v += u;
        }
        wsum[lane] = v;
    }
    __syncthreads();
    int warpbase = (w > 0) ? wsum[w - 1] : 0;
    int base = warpbase + inc - sum;
    #pragma unroll
    for (int j = 0; j < 10; j++) {
        int idx = base_i + j;
        if (idx < NN) { int r = base + loc[j]; g_rs[idx] = r; g_cur[idx] = r; }
    }
    if (t == 1023) g_rs[NN] = wsum[31];
}

__global__ void k_scatter() {
    int i = blockIdx.x * blockDim.x + threadIdx.x;
    if (i >= NE) return;
    int pos = atomicAdd(&g_cur[g_dst[i]], 1);
    g_csrc[pos] = g_src[i];
}

// ---------------- hi/lo split (layer-1 input only) ---------------------------
__global__ void k_split(const float* __restrict__ a, __nv_bfloat16* __restrict__ hi,
                        __nv_bfloat16* __restrict__ lo, int n) {
    int i = blockIdx.x * blockDim.x + threadIdx.x;
    if (i >= n) return;
    float v = a[i];
    __nv_bfloat16 h = __float2bfloat16_rn(v);
    hi[i] = h;
    lo[i] = __float2bfloat16_rn(v - __bfloat162float(h));
}

// ---------------- coalesced weight prep: W[K,M] -> WT[m+rofs][K] hi/lo -------
__global__ __launch_bounds__(256) void k_prep_w(
    const float* __restrict__ W, __nv_bfloat16* __restrict__ hiT,
    __nv_bfloat16* __restrict__ loT, int K, int M, int rofs) {
    __shared__ float s[64][33];
    int k0 = blockIdx.x * 64, m0 = blockIdx.y * 32;
    int tid = threadIdx.x;
    #pragma unroll
    for (int i = tid; i < 64 * 32; i += 256) {
        int kk = i >> 5, mm = i & 31;
        s[kk][mm] = W[(size_t)(k0 + kk) * M + m0 + mm];
    }
    __syncthreads();
    #pragma unroll
    for (int i = tid; i < 32 * 32; i += 256) {
        int mm = i >> 5, kp = i & 31;
        float v0 = s[2 * kp][mm], v1 = s[2 * kp + 1][mm];
        __nv_bfloat162 h2 = __floats2bfloat162_rn(v0, v1);
        float l0 = v0 - __bfloat162float(__low2bfloat16(h2));
        float l1 = v1 - __bfloat162float(__high2bfloat16(h2));
        __nv_bfloat162 l2 = __floats2bfloat162_rn(l0, l1);
        size_t ro = (size_t)(m0 + mm + rofs) * K + k0 + 2 * kp;
        *(uint32_t*)(hiT + ro) = *(uint32_t*)&h2;
        *(uint32_t*)(loT + ro) = *(uint32_t*)&l2;
    }
}

// ---------------- cp.async + ldmatrix bf16 GEMM (3-pass hi/lo) --------------
#define TPAD 40
#define TILE_E (128 * TPAD)
#define STAGE_E (4 * TILE_E)
#define SMEM_GEMM (2 * STAGE_E * 2)

__device__ __forceinline__ void cpa16(uint32_t dst, const void* src, int sz) {
    asm volatile("cp.async.cg.shared.global [%0], [%1], 16, %2;"
                 :: "r"(dst), "l"(src), "r"(sz) : "memory");
}
__device__ __forceinline__ void cpa_commit() {
    asm volatile("cp.async.commit_group;" ::: "memory");
}
template<int N> __device__ __forceinline__ void cpa_wait() {
    asm volatile("cp.async.wait_group %0;" :: "n"(N) : "memory");
}
__device__ __forceinline__ void ldsm4(uint32_t* r, uint32_t addr) {
    asm volatile("ldmatrix.sync.aligned.m8n8.x4.shared.b16 {%0,%1,%2,%3}, [%4];"
                 : "=r"(r[0]), "=r"(r[1]), "=r"(r[2]), "=r"(r[3]) : "r"(addr));
}

// mode bit0: bias + leaky(0.1); mode bit1: also write bf16 hi/lo to Hi/Lo[r*M+c]
__global__ __launch_bounds__(256) void k_gemm_mma(
    const __nv_bfloat16* __restrict__ Ahi, const __nv_bfloat16* __restrict__ Alo,
    const __nv_bfloat16* __restrict__ BhiT, const __nv_bfloat16* __restrict__ BloT,
    float* __restrict__ C, int Nrows, int K, int M,
    const float* __restrict__ bias, int mode,
    __nv_bfloat16* __restrict__ Hi, __nv_bfloat16* __restrict__ Lo)
{
    extern __shared__ __nv_bfloat16 smem[];
    uint32_t sb = (uint32_t)__cvta_generic_to_shared(smem);

    int tid = threadIdx.x;
    int wid = tid >> 5, lane = tid & 31;
    int wm = wid & 1, wn = wid >> 1;
    int row0 = blockIdx.y * 128;
    int col0 = blockIdx.x * 128;
    int mBase = wm * 64, nBase = wn * 32;
    int g = lane >> 2, cw = lane & 3;
    int mat = lane >> 3, r8 = lane & 7;
    int rsel = (mat & 1) * 8 + r8;
    int csel = (mat >> 1) * 8;

    float acc[4][4][4];
    #pragma unroll
    for (int a = 0; a < 4; a++)
        #pragma unroll
        for (int b = 0; b < 4; b++)
            #pragma unroll
            for (int c = 0; c < 4; c++) acc[a][b][c] = 0.f;

    int nk = K / 32;
    int c0 = tid * 2;

    auto prefetch = [&](int ck, int stage) {
        int kofs = ck * 32;
        uint32_t se = (uint32_t)stage * STAGE_E;
        #pragma unroll
        for (int i = 0; i < 2; i++) {
            int c = c0 + i;
            int r = c >> 2, seg = c & 3;
            uint32_t dA = sb + 2 * (se + r * TPAD + seg * 8);
            int gr = row0 + r;
            int szA = (gr < Nrows) ? 16 : 0;
            const __nv_bfloat16* pa = Ahi + (size_t)gr * K + kofs + seg * 8;
            const __nv_bfloat16* pl = Alo + (size_t)gr * K + kofs + seg * 8;
            if (szA == 0) { pa = Ahi; pl = Alo; }
            cpa16(dA, pa, szA);
            cpa16(dA + 2 * TILE_E, pl, szA);
            const __nv_bfloat16* pb = BhiT + (size_t)(col0 + r) * K + kofs + seg * 8;
            const __nv_bfloat16* pq = BloT + (size_t)(col0 + r) * K + kofs + seg * 8;
            cpa16(dA + 2 * (2 * TILE_E), pb, 16);
            cpa16(dA + 2 * (3 * TILE_E), pq, 16);
        }
        cpa_commit();
    };

    prefetch(0, 0);

    for (int ck = 0; ck < nk; ck++) {
        int stage = ck & 1;
        if (ck + 1 < nk) { prefetch(ck + 1, stage ^ 1); cpa_wait<1>(); }
        else             { cpa_wait<0>(); }
        __syncthreads();

        uint32_t se = (uint32_t)stage * STAGE_E;
        #pragma unroll
        for (int pass = 0; pass < 3; pass++) {
            uint32_t aoff = se + ((pass == 1) ? TILE_E : 0u);
            uint32_t boff = se + ((pass == 2) ? 3u * TILE_E : 2u * TILE_E);
            #pragma unroll
            for (int ks = 0; ks < 2; ks++) {
                int kw = ks * 16 + csel;
                uint32_t af[4][4];
                #pragma unroll
                for (int mi = 0; mi < 4; mi++)
                    ldsm4(af[mi], sb + 2 * (aoff + (uint32_t)(mBase + mi * 16 + rsel) * TPAD + kw));
                uint32_t bfr[2][4];
                #pragma unroll
                for (int p = 0; p < 2; p++)
                    ldsm4(bfr[p], sb + 2 * (boff + (uint32_t)(nBase + p * 16 + rsel) * TPAD + kw));
                #pragma unroll
                for (int mi = 0; mi < 4; mi++)
                    #pragma unroll
                    for (int ni = 0; ni < 4; ni++) {
                        float* d = acc[mi][ni];
                        uint32_t b0 = bfr[ni >> 1][ni & 1];
                        uint32_t b1 = bfr[ni >> 1][2 + (ni & 1)];
                        asm volatile(
                            "mma.sync.aligned.m16n8k16.row.col.f32.bf16.bf16.f32 "
                            "{%0,%1,%2,%3}, {%4,%5,%6,%7}, {%8,%9}, {%0,%1,%2,%3};"
                            : "+f"(d[0]), "+f"(d[1]), "+f"(d[2]), "+f"(d[3])
                            : "r"(af[mi][0]), "r"(af[mi][1]), "r"(af[mi][2]), "r"(af[mi][3]),
                              "r"(b0), "r"(b1));
                    }
            }
        }
        __syncthreads();
    }

    #pragma unroll
    for (int mi = 0; mi < 4; mi++) {
        int r0 = row0 + mBase + mi * 16 + g;
        #pragma unroll
        for (int ni = 0; ni < 4; ni++) {
            int cc = col0 + nBase + ni * 8 + cw * 2;
            float v0 = acc[mi][ni][0], v1 = acc[mi][ni][1];
            float v2 = acc[mi][ni][2], v3 = acc[mi][ni][3];
            if (mode & 1) {
                float b0 = bias[cc], b1 = bias[cc + 1];
                v0 += b0; v0 = (v0 > 0.f) ? v0 : 0.1f * v0;
                v1 += b1; v1 = (v1 > 0.f) ? v1 : 0.1f * v1;
                v2 += b0; v2 = (v2 > 0.f) ? v2 : 0.1f * v2;
                v3 += b1; v3 = (v3 > 0.f) ? v3 : 0.1f * v3;
            }
            if (r0 < Nrows) {
                *(float2*)(C + (size_t)r0 * M + cc) = make_float2(v0, v1);
                if (mode & 2) {
                    __nv_bfloat162 h2 = __floats2bfloat162_rn(v0, v1);
                    float l0 = v0 - __bfloat162float(__low2bfloat16(h2));
                    float l1 = v1 - __bfloat162float(__high2bfloat16(h2));
                    __nv_bfloat162 l2 = __floats2bfloat162_rn(l0, l1);
                    *(uint32_t*)(Hi + (size_t)r0 * M + cc) = *(uint32_t*)&h2;
                    *(uint32_t*)(Lo + (size_t)r0 * M + cc) = *(uint32_t*)&l2;
                }
            }
            if (r0 + 8 < Nrows) {
                *(float2*)(C + (size_t)(r0 + 8) * M + cc) = make_float2(v2, v3);
                if (mode & 2) {
                    __nv_bfloat162 h2 = __floats2bfloat162_rn(v2, v3);
                    float l0 = v2 - __bfloat162float(__low2bfloat16(h2));
                    float l1 = v3 - __bfloat162float(__high2bfloat16(h2));
                    __nv_bfloat162 l2 = __floats2bfloat162_rn(l0, l1);
                    *(uint32_t*)(Hi + (size_t)(r0 + 8) * M + cc) = *(uint32_t*)&h2;
                    *(uint32_t*)(Lo + (size_t)(r0 + 8) * M + cc) = *(uint32_t*)&l2;
                }
            }
        }
    }
}

// ---------------- fused GATv2 edge kernel: one-pass online softmax ----------
// one warp per dst; each edge's xl row is loaded ONCE and used for both the
// attention logit and the weighted accumulation (running-max rescale).
__global__ __launch_bounds__(256) void k_gat_edge(const float* __restrict__ att,
                                                  const float* __restrict__ bias) {
    int gw = (blockIdx.x * 256 + threadIdx.x) >> 5;
    int lane = threadIdx.x & 31;
    if (gw >= NN) return;
    int d = gw;
    int rs = g_rs[d], re = g_rs[d + 1];

    float4 xr4[4], at4[4];
    const float4* pxr = (const float4*)(g_xlr + (size_t)d * 1024 + 512);
    const float4* pat = (const float4*)att;
    #pragma unroll
    for (int j = 0; j < 4; j++) {
        xr4[j] = pxr[j * 32 + lane];
        at4[j] = pat[j * 32 + lane];
    }

    float m = -3.0e38f;
    float den = 0.f;
    float accf[16];
    #pragma unroll
    for (int j = 0; j < 16; j++) accf[j] = 0.f;

    for (int e = rs; e < re; e++) {
        int s = g_csrc[e];
        const float4* pxl = (const float4*)(g_xlr + (size_t)s * 1024);
        float4 a[4];
        float lg = 0.f;
        #pragma unroll
        for (int j = 0; j < 4; j++) {
            a[j] = pxl[j * 32 + lane];
            float v;
            v = a[j].x + xr4[j].x; v = v > 0.f ? v : 0.2f * v; lg += v * at4[j].x;
            v = a[j].y + xr4[j].y; v = v > 0.f ? v : 0.2f * v; lg += v * at4[j].y;
            v = a[j].z + xr4[j].z; v = v > 0.f ? v : 0.2f * v; lg += v * at4[j].z;
            v = a[j].w + xr4[j].w; v = v > 0.f ? v : 0.2f * v; lg += v * at4[j].w;
        }
        #pragma unroll
        for (int o = 16; o; o >>= 1) lg += __shfl_xor_sync(0xffffffffu, lg, o);

        if (lg > m) {                     // rescale state to new max
            float scale = expf(m - lg);   // first edge: exp(-inf)=0 zeroes state
            den *= scale;
            #pragma unroll
            for (int j = 0; j < 16; j++) accf[j] *= scale;
            m = lg;
        }
        float w = expf(lg - m);
        den += w;
        #pragma unroll
        for (int j = 0; j < 4; j++) {
            accf[4 * j + 0] += w * a[j].x;
            accf[4 * j + 1] += w * a[j].y;
            accf[4 * j + 2] += w * a[j].z;
            accf[4 * j + 3] += w * a[j].w;
        }
    }

    float inv = 1.0f / (den + 1e-16f);
    const float4* pb = (const float4*)bias;
    __nv_bfloat16* ph = g_ahi + (size_t)d * DE;
    __nv_bfloat16* pl = g_alo + (size_t)d * DE;
    #pragma unroll
    for (int j = 0; j < 4; j++) {
        float4 b = pb[j * 32 + lane];
        float t0 = tanhf(accf[4 * j + 0] * inv + b.x);
        float t1 = tanhf(accf[4 * j + 1] * inv + b.y);
        float t2 = tanhf(accf[4 * j + 2] * inv + b.z);
        float t3 = tanhf(accf[4 * j + 3] * inv + b.w);
        __nv_bfloat162 h01 = __floats2bfloat162_rn(t0, t1);
        __nv_bfloat162 h23 = __floats2bfloat162_rn(t2, t3);
        float l0 = t0 - __bfloat162float(__low2bfloat16(h01));
        float l1 = t1 - __bfloat162float(__high2bfloat16(h01));
        float l2 = t2 - __bfloat162float(__low2bfloat16(h23));
        float l3 = t3 - __bfloat162float(__high2bfloat16(h23));
        __nv_bfloat162 q01 = __floats2bfloat162_rn(l0, l1);
        __nv_bfloat162 q23 = __floats2bfloat162_rn(l2, l3);
        uint2 uh, ul;
        uh.x = *(uint32_t*)&h01; uh.y = *(uint32_t*)&h23;
        ul.x = *(uint32_t*)&q01; ul.y = *(uint32_t*)&q23;
        ((uint2*)ph)[j * 32 + lane] = uh;
        ((uint2*)pl)[j * 32 + lane] = ul;
    }
}

// ---------------- final MLP tail --------------------------------------------
__global__ void k_dot3(const float* __restrict__ A3, const float* __restrict__ c3) {
    int gt = blockIdx.x * blockDim.x + threadIdx.x;
    int n = gt >> 5;
    int lane = gt & 31;
    if (n >= NN) return;
    const float4* pm = (const float4*)(g_m2 + (size_t)n * DH);
    const float4* pw = (const float4*)A3;
    float acc = 0.f;
    #pragma unroll
    for (int i = 0; i < DH / 128; i++) {
        int k = i * 32 + lane;
        float4 m = pm[k], w = pw[k];
        acc += m.x * w.x + m.y * w.y + m.z * w.z + m.w * w.w;
    }
    #pragma unroll
    for (int o = 16; o; o >>= 1) acc += __shfl_xor_sync(0xffffffffu, acc, o);
    if (lane == 0) g_logit[n] = acc + c3[0];
}

__global__ void k_softmax(float* __restrict__ out) {
    __shared__ float sh[1024];
    int t = threadIdx.x;
    float m = -3.0e38f;
    for (int i = t; i < NN; i += 1024) m = fmaxf(m, g_logit[i]);
    sh[t] = m; __syncthreads();
    for (int s = 512; s; s >>= 1) { if (t < s) sh[t] = fmaxf(sh[t], sh[t + s]); __syncthreads(); }
    float gm = sh[0]; __syncthreads();
    float sum = 0.f;
    for (int i = t; i < NN; i += 1024) sum += expf(g_logit[i] - gm);
    sh[t] = sum; __syncthreads();
    for (int s = 512; s; s >>= 1) { if (t < s) sh[t] += sh[t + s]; __syncthreads(); }
    float gs = sh[0];
    for (int i = t; i < NN; i += 1024) out[i] = expf(g_logit[i] - gm) / gs;
}

// ---------------- host side -------------------------------------------------
static __nv_bfloat16 *s_ahi, *s_alo, *s_whi, *s_wlo;

static void run_gemm(int K, int M, float* Cout, const float* bias, int mode) {
    dim3 g(M / 128, (NN + 127) / 128);
    k_gemm_mma<<<g, 256, SMEM_GEMM>>>(s_ahi, s_alo, s_whi, s_wlo, Cout, NN, K, M,
                                      bias, mode, s_ahi, s_alo);
}

static void prep_w(const float* W, int K, int M, int rofs) {
    dim3 g(K / 64, M / 32);
    k_prep_w<<<g, 256>>>(W, s_whi, s_wlo, K, M, rofs);
}

static void gat_layer(int din, const float* Wl, const float* Wr,
                      const float* att, const float* bias, float* xlr) {
    prep_w(Wl, din, DE, 0);
    prep_w(Wr, din, DE, DE);
    run_gemm(din, 2 * DE, xlr, nullptr, 0);
    k_gat_edge<<<(NN * 32 + 255) / 256, 256>>>(att, bias);
}

extern "C" void kernel_launch(void* const* d_in, const int* in_sizes, int n_in,
                              void* d_out, int out_size) {
    const float* x   = (const float*)d_in[0];
    const int*   ei  = (const int*)d_in[1];
    const float* Wl1 = (const float*)d_in[2];
    const float* Wr1 = (const float*)d_in[3];
    const float* at1 = (const float*)d_in[4];
    const float* b1  = (const float*)d_in[5];
    const float* Wl2 = (const float*)d_in[6];
    const float* Wr2 = (const float*)d_in[7];
    const float* at2 = (const float*)d_in[8];
    const float* b2  = (const float*)d_in[9];
    const float* Wl3 = (const float*)d_in[10];
    const float* Wr3 = (const float*)d_in[11];
    const float* at3 = (const float*)d_in[12];
    const float* b3  = (const float*)d_in[13];
    const float* A1  = (const float*)d_in[14];
    const float* c1  = (const float*)d_in[15];
    const float* A2  = (const float*)d_in[16];
    const float* c2  = (const float*)d_in[17];
    const float* A3  = (const float*)d_in[18];
    const float* c3  = (const float*)d_in[19];
    float* out = (float*)d_out;

    cudaFuncSetAttribute(k_gemm_mma, cudaFuncAttributeMaxDynamicSharedMemorySize, SMEM_GEMM);

    float *xlr, *m1, *m2;
    cudaGetSymbolAddress((void**)&xlr, g_xlr);
    cudaGetSymbolAddress((void**)&m1,  g_m1);
    cudaGetSymbolAddress((void**)&m2,  g_m2);
    cudaGetSymbolAddress((void**)&s_ahi, g_ahi);
    cudaGetSymbolAddress((void**)&s_alo, g_alo);
    cudaGetSymbolAddress((void**)&s_whi, g_whi);
    cudaGetSymbolAddress((void**)&s_wlo, g_wlo);

    // edges + CSR by dst
    k_detect<<<1, 256>>>(ei);
    k_edges<<<(NE + 255) / 256, 256>>>(ei);
    k_hist<<<(NE + 255) / 256, 256>>>();
    k_scan<<<1, 1024>>>();
    k_scatter<<<(NE + 255) / 256, 256>>>();

    // layer 1 input split
    k_split<<<(NN * DI + 255) / 256, 256>>>(x, s_ahi, s_alo, NN * DI);

    gat_layer(DI, Wl1, Wr1, at1, b1, xlr);
    gat_layer(DE, Wl2, Wr2, at2, b2, xlr);
    gat_layer(DE, Wl3, Wr3, at3, b3, xlr);

    // MLP: gemm epilogue fuses bias+leaky (+hi/lo split for the next gemm)
    prep_w(A1, DE, DH, 0);
    run_gemm(DE, DH, m1, c1, 3);
    prep_w(A2, DH, DH, 0);
    run_gemm(DH, DH, m2, c2, 1);
    k_dot3<<<(NN * 32 + 255) / 256, 256>>>(A3, c3);
    k_softmax<<<1, 1024>>>(out);
}

// round 11
// speedup vs baseline: 2.2750x; 1.0714x over previous
#include <cuda_runtime.h>
#include <cuda_bf16.h>
#include <math.h>
#include <stdint.h>

#define NN 10000
#define NE 160000
#define DI 128
#define DE 512
#define DH 256

// ---------------- scratch (device globals; no allocation allowed) ----------
__device__ __align__(16) float g_xlr[NN * 2 * DE];   // [node][xl(512) | xr(512)]
__device__ int   g_src[NE];
__device__ int   g_dst[NE];
__device__ int   g_deg[NN];
__device__ int   g_rs[NN + 1];
__device__ int   g_cur[NN];
__device__ int   g_csrc[NE];
__device__ __align__(16) float g_m1[NN * DH];
__device__ __align__(16) float g_m2[NN * DH];
__device__ float g_logit[NN];
__device__ int   g_is64;
__device__ __align__(16) __nv_bfloat16 g_ahi[NN * DE];
__device__ __align__(16) __nv_bfloat16 g_alo[NN * DE];
__device__ __align__(16) __nv_bfloat16 g_whi[2 * DE * DE];
__device__ __align__(16) __nv_bfloat16 g_wlo[2 * DE * DE];

// ---------------- edge decode (+ degree histogram fused) --------------------
__global__ void k_detect(const int* __restrict__ w) {
    __shared__ int s;
    if (threadIdx.x == 0) s = 0;
    __syncthreads();
    int acc = 0;
    for (int i = threadIdx.x; i < 2048; i += 256) acc |= w[2 * i + 1];
    atomicOr(&s, acc);
    for (int i = threadIdx.x; i < NN; i += 256) g_deg[i] = 0;
    __syncthreads();
    if (threadIdx.x == 0) g_is64 = (s == 0) ? 1 : 0;
}

__global__ void k_edges(const int* __restrict__ w) {
    int i = blockIdx.x * blockDim.x + threadIdx.x;
    if (i >= NE) return;
    int s, d;
    if (g_is64) { s = w[2 * i]; d = w[2 * (NE + i)]; }
    else        { s = w[i];     d = w[NE + i]; }
    if ((unsigned)s >= NN) s = 0;
    if ((unsigned)d >= NN) d = 0;
    g_src[i] = s;
    g_dst[i] = d;
    atomicAdd(&g_deg[d], 1);
}

// coalesced chunked scan: 10 chunks of 1024, warp-shuffle within chunk
__global__ void k_scan() {
    __shared__ int wsum[32];
    __shared__ int sbase;
    int t = threadIdx.x;
    int lane = t & 31, w = t >> 5;
    if (t == 0) sbase = 0;
    __syncthreads();
    for (int c = 0; c < NN; c += 1024) {
        int idx = c + t;
        int v = (idx < NN) ? g_deg[idx] : 0;
        int inc = v;
        #pragma unroll
        for (int o = 1; o < 32; o <<= 1) {
            int u = __shfl_up_sync(0xffffffffu, inc, o);
            if (lane >= o) inc += u;
        }
        if (lane == 31) wsum[w] = inc;
        __syncthreads();
        if (w == 0) {
            int vv = wsum[lane];
            #pragma unroll
            for (int o = 1; o < 32; o <<= 1) {
                int u = __shfl_up_sync(0xffffffffu, vv, o);
                if (lane >= o) vv += u;
            }
            wsum[lane] = vv;
        }
        __syncthreads();
        int base = sbase + ((w > 0) ? wsum[w - 1] : 0) + inc - v;
        if (idx < NN) { g_rs[idx] = base; g_cur[idx] = base; }
        __syncthreads();
        if (t == 0) sbase += wsum[31];
        __syncthreads();
    }
    if (t == 0) g_rs[NN] = sbase;
}

__global__ void k_scatter() {
    int i = blockIdx.x * blockDim.x + threadIdx.x;
    if (i >= NE) return;
    int pos = atomicAdd(&g_cur[g_dst[i]], 1);
    g_csrc[pos] = g_src[i];
}

// ---------------- hi/lo split (layer-1 input only) ---------------------------
__global__ void k_split(const float* __restrict__ a, __nv_bfloat16* __restrict__ hi,
                        __nv_bfloat16* __restrict__ lo, int n) {
    int i = blockIdx.x * blockDim.x + threadIdx.x;
    if (i >= n) return;
    float v = a[i];
    __nv_bfloat16 h = __float2bfloat16_rn(v);
    hi[i] = h;
    lo[i] = __float2bfloat16_rn(v - __bfloat162float(h));
}

// ---------------- coalesced weight prep: W[K,M] -> WT[m+rofs][K] hi/lo -------
__global__ __launch_bounds__(256) void k_prep_w(
    const float* __restrict__ W, __nv_bfloat16* __restrict__ hiT,
    __nv_bfloat16* __restrict__ loT, int K, int M, int rofs) {
    __shared__ float s[64][33];
    int k0 = blockIdx.x * 64, m0 = blockIdx.y * 32;
    int tid = threadIdx.x;
    #pragma unroll
    for (int i = tid; i < 64 * 32; i += 256) {
        int kk = i >> 5, mm = i & 31;
        s[kk][mm] = W[(size_t)(k0 + kk) * M + m0 + mm];
    }
    __syncthreads();
    #pragma unroll
    for (int i = tid; i < 32 * 32; i += 256) {
        int mm = i >> 5, kp = i & 31;
        float v0 = s[2 * kp][mm], v1 = s[2 * kp + 1][mm];
        __nv_bfloat162 h2 = __floats2bfloat162_rn(v0, v1);
        float l0 = v0 - __bfloat162float(__low2bfloat16(h2));
        float l1 = v1 - __bfloat162float(__high2bfloat16(h2));
        __nv_bfloat162 l2 = __floats2bfloat162_rn(l0, l1);
        size_t ro = (size_t)(m0 + mm + rofs) * K + k0 + 2 * kp;
        *(uint32_t*)(hiT + ro) = *(uint32_t*)&h2;
        *(uint32_t*)(loT + ro) = *(uint32_t*)&l2;
    }
}

// ---------------- cp.async + ldmatrix bf16 GEMM (3-pass hi/lo) --------------
#define TPAD 40
#define TILE_E (128 * TPAD)
#define STAGE_E (4 * TILE_E)
#define SMEM_GEMM (2 * STAGE_E * 2)

__device__ __forceinline__ void cpa16(uint32_t dst, const void* src, int sz) {
    asm volatile("cp.async.cg.shared.global [%0], [%1], 16, %2;"
                 :: "r"(dst), "l"(src), "r"(sz) : "memory");
}
__device__ __forceinline__ void cpa_commit() {
    asm volatile("cp.async.commit_group;" ::: "memory");
}
template<int N> __device__ __forceinline__ void cpa_wait() {
    asm volatile("cp.async.wait_group %0;" :: "n"(N) : "memory");
}
__device__ __forceinline__ void ldsm4(uint32_t* r, uint32_t addr) {
    asm volatile("ldmatrix.sync.aligned.m8n8.x4.shared.b16 {%0,%1,%2,%3}, [%4];"
                 : "=r"(r[0]), "=r"(r[1]), "=r"(r[2]), "=r"(r[3]) : "r"(addr));
}

// mode bit0: bias + leaky(0.1); mode bit1: also write bf16 hi/lo to Hi/Lo[r*M+c]
__global__ __launch_bounds__(256, 2) void k_gemm_mma(
    const __nv_bfloat16* __restrict__ Ahi, const __nv_bfloat16* __restrict__ Alo,
    const __nv_bfloat16* __restrict__ BhiT, const __nv_bfloat16* __restrict__ BloT,
    float* __restrict__ C, int Nrows, int K, int M,
    const float* __restrict__ bias, int mode,
    __nv_bfloat16* __restrict__ Hi, __nv_bfloat16* __restrict__ Lo)
{
    extern __shared__ __nv_bfloat16 smem[];
    uint32_t sb = (uint32_t)__cvta_generic_to_shared(smem);

    int tid = threadIdx.x;
    int wid = tid >> 5, lane = tid & 31;
    int wm = wid & 1, wn = wid >> 1;
    int row0 = blockIdx.y * 128;
    int col0 = blockIdx.x * 128;
    int mBase = wm * 64, nBase = wn * 32;
    int g = lane >> 2, cw = lane & 3;
    int mat = lane >> 3, r8 = lane & 7;
    int rsel = (mat & 1) * 8 + r8;
    int csel = (mat >> 1) * 8;

    float acc[4][4][4];
    #pragma unroll
    for (int a = 0; a < 4; a++)
        #pragma unroll
        for (int b = 0; b < 4; b++)
            #pragma unroll
            for (int c = 0; c < 4; c++) acc[a][b][c] = 0.f;

    int nk = K / 32;
    int c0 = tid * 2;

    auto prefetch = [&](int ck, int stage) {
        int kofs = ck * 32;
        uint32_t se = (uint32_t)stage * STAGE_E;
        #pragma unroll
        for (int i = 0; i < 2; i++) {
            int c = c0 + i;
            int r = c >> 2, seg = c & 3;
            uint32_t dA = sb + 2 * (se + r * TPAD + seg * 8);
            int gr = row0 + r;
            int szA = (gr < Nrows) ? 16 : 0;
            const __nv_bfloat16* pa = Ahi + (size_t)gr * K + kofs + seg * 8;
            const __nv_bfloat16* pl = Alo + (size_t)gr * K + kofs + seg * 8;
            if (szA == 0) { pa = Ahi; pl = Alo; }
            cpa16(dA, pa, szA);
            cpa16(dA + 2 * TILE_E, pl, szA);
            const __nv_bfloat16* pb = BhiT + (size_t)(col0 + r) * K + kofs + seg * 8;
            const __nv_bfloat16* pq = BloT + (size_t)(col0 + r) * K + kofs + seg * 8;
            cpa16(dA + 2 * (2 * TILE_E), pb, 16);
            cpa16(dA + 2 * (3 * TILE_E), pq, 16);
        }
        cpa_commit();
    };

    prefetch(0, 0);

    for (int ck = 0; ck < nk; ck++) {
        int stage = ck & 1;
        if (ck + 1 < nk) { prefetch(ck + 1, stage ^ 1); cpa_wait<1>(); }
        else             { cpa_wait<0>(); }
        __syncthreads();

        uint32_t se = (uint32_t)stage * STAGE_E;
        #pragma unroll
        for (int pass = 0; pass < 3; pass++) {
            uint32_t aoff = se + ((pass == 1) ? TILE_E : 0u);
            uint32_t boff = se + ((pass == 2) ? 3u * TILE_E : 2u * TILE_E);
            #pragma unroll
            for (int ks = 0; ks < 2; ks++) {
                int kw = ks * 16 + csel;
                uint32_t af[4][4];
                #pragma unroll
                for (int mi = 0; mi < 4; mi++)
                    ldsm4(af[mi], sb + 2 * (aoff + (uint32_t)(mBase + mi * 16 + rsel) * TPAD + kw));
                uint32_t bfr[2][4];
                #pragma unroll
                for (int p = 0; p < 2; p++)
                    ldsm4(bfr[p], sb + 2 * (boff + (uint32_t)(nBase + p * 16 + rsel) * TPAD + kw));
                #pragma unroll
                for (int mi = 0; mi < 4; mi++)
                    #pragma unroll
                    for (int ni = 0; ni < 4; ni++) {
                        float* d = acc[mi][ni];
                        uint32_t b0 = bfr[ni >> 1][ni & 1];
                        uint32_t b1 = bfr[ni >> 1][2 + (ni & 1)];
                        asm volatile(
                            "mma.sync.aligned.m16n8k16.row.col.f32.bf16.bf16.f32 "
                            "{%0,%1,%2,%3}, {%4,%5,%6,%7}, {%8,%9}, {%0,%1,%2,%3};"
                            : "+f"(d[0]), "+f"(d[1]), "+f"(d[2]), "+f"(d[3])
                            : "r"(af[mi][0]), "r"(af[mi][1]), "r"(af[mi][2]), "r"(af[mi][3]),
                              "r"(b0), "r"(b1));
                    }
            }
        }
        __syncthreads();
    }

    #pragma unroll
    for (int mi = 0; mi < 4; mi++) {
        int r0 = row0 + mBase + mi * 16 + g;
        #pragma unroll
        for (int ni = 0; ni < 4; ni++) {
            int cc = col0 + nBase + ni * 8 + cw * 2;
            float v0 = acc[mi][ni][0], v1 = acc[mi][ni][1];
            float v2 = acc[mi][ni][2], v3 = acc[mi][ni][3];
            if (mode & 1) {
                float b0 = bias[cc], b1 = bias[cc + 1];
                v0 += b0; v0 = (v0 > 0.f) ? v0 : 0.1f * v0;
                v1 += b1; v1 = (v1 > 0.f) ? v1 : 0.1f * v1;
                v2 += b0; v2 = (v2 > 0.f) ? v2 : 0.1f * v2;
                v3 += b1; v3 = (v3 > 0.f) ? v3 : 0.1f * v3;
            }
            if (r0 < Nrows) {
                *(float2*)(C + (size_t)r0 * M + cc) = make_float2(v0, v1);
                if (mode & 2) {
                    __nv_bfloat162 h2 = __floats2bfloat162_rn(v0, v1);
                    float l0 = v0 - __bfloat162float(__low2bfloat16(h2));
                    float l1 = v1 - __bfloat162float(__high2bfloat16(h2));
                    __nv_bfloat162 l2 = __floats2bfloat162_rn(l0, l1);
                    *(uint32_t*)(Hi + (size_t)r0 * M + cc) = *(uint32_t*)&h2;
                    *(uint32_t*)(Lo + (size_t)r0 * M + cc) = *(uint32_t*)&l2;
                }
            }
            if (r0 + 8 < Nrows) {
                *(float2*)(C + (size_t)(r0 + 8) * M + cc) = make_float2(v2, v3);
                if (mode & 2) {
                    __nv_bfloat162 h2 = __floats2bfloat162_rn(v2, v3);
                    float l0 = v2 - __bfloat162float(__low2bfloat16(h2));
                    float l1 = v3 - __bfloat162float(__high2bfloat16(h2));
                    __nv_bfloat162 l2 = __floats2bfloat162_rn(l0, l1);
                    *(uint32_t*)(Hi + (size_t)(r0 + 8) * M + cc) = *(uint32_t*)&h2;
                    *(uint32_t*)(Lo + (size_t)(r0 + 8) * M + cc) = *(uint32_t*)&l2;
                }
            }
        }
    }
}

// ---------------- fused GATv2 edge kernel: one-pass online softmax ----------
__global__ __launch_bounds__(256) void k_gat_edge(const float* __restrict__ att,
                                                  const float* __restrict__ bias) {
    int gw = (blockIdx.x * 256 + threadIdx.x) >> 5;
    int lane = threadIdx.x & 31;
    if (gw >= NN) return;
    int d = gw;
    int rs = g_rs[d], re = g_rs[d + 1];

    float4 xr4[4], at4[4];
    const float4* pxr = (const float4*)(g_xlr + (size_t)d * 1024 + 512);
    const float4* pat = (const float4*)att;
    #pragma unroll
    for (int j = 0; j < 4; j++) {
        xr4[j] = pxr[j * 32 + lane];
        at4[j] = pat[j * 32 + lane];
    }

    float m = -3.0e38f;
    float den = 0.f;
    float accf[16];
    #pragma unroll
    for (int j = 0; j < 16; j++) accf[j] = 0.f;

    for (int e = rs; e < re; e++) {
        int s = g_csrc[e];
        const float4* pxl = (const float4*)(g_xlr + (size_t)s * 1024);
        float4 a[4];
        float lg = 0.f;
        #pragma unroll
        for (int j = 0; j < 4; j++) {
            a[j] = pxl[j * 32 + lane];
            float v;
            v = a[j].x + xr4[j].x; v = v > 0.f ? v : 0.2f * v; lg += v * at4[j].x;
            v = a[j].y + xr4[j].y; v = v > 0.f ? v : 0.2f * v; lg += v * at4[j].y;
            v = a[j].z + xr4[j].z; v = v > 0.f ? v : 0.2f * v; lg += v * at4[j].z;
            v = a[j].w + xr4[j].w; v = v > 0.f ? v : 0.2f * v; lg += v * at4[j].w;
        }
        #pragma unroll
        for (int o = 16; o; o >>= 1) lg += __shfl_xor_sync(0xffffffffu, lg, o);

        if (lg > m) {
            float scale = expf(m - lg);
            den *= scale;
            #pragma unroll
            for (int j = 0; j < 16; j++) accf[j] *= scale;
            m = lg;
        }
        float w = expf(lg - m);
        den += w;
        #pragma unroll
        for (int j = 0; j < 4; j++) {
            accf[4 * j + 0] += w * a[j].x;
            accf[4 * j + 1] += w * a[j].y;
            accf[4 * j + 2] += w * a[j].z;
            accf[4 * j + 3] += w * a[j].w;
        }
    }

    float inv = 1.0f / (den + 1e-16f);
    const float4* pb = (const float4*)bias;
    __nv_bfloat16* ph = g_ahi + (size_t)d * DE;
    __nv_bfloat16* pl = g_alo + (size_t)d * DE;
    #pragma unroll
    for (int j = 0; j < 4; j++) {
        float4 b = pb[j * 32 + lane];
        float t0 = tanhf(accf[4 * j + 0] * inv + b.x);
        float t1 = tanhf(accf[4 * j + 1] * inv + b.y);
        float t2 = tanhf(accf[4 * j + 2] * inv + b.z);
        float t3 = tanhf(accf[4 * j + 3] * inv + b.w);
        __nv_bfloat162 h01 = __floats2bfloat162_rn(t0, t1);
        __nv_bfloat162 h23 = __floats2bfloat162_rn(t2, t3);
        float l0 = t0 - __bfloat162float(__low2bfloat16(h01));
        float l1 = t1 - __bfloat162float(__high2bfloat16(h01));
        float l2 = t2 - __bfloat162float(__low2bfloat16(h23));
        float l3 = t3 - __bfloat162float(__high2bfloat16(h23));
        __nv_bfloat162 q01 = __floats2bfloat162_rn(l0, l1);
        __nv_bfloat162 q23 = __floats2bfloat162_rn(l2, l3);
        uint2 uh, ul;
        uh.x = *(uint32_t*)&h01; uh.y = *(uint32_t*)&h23;
        ul.x = *(uint32_t*)&q01; ul.y = *(uint32_t*)&q23;
        ((uint2*)ph)[j * 32 + lane] = uh;
        ((uint2*)pl)[j * 32 + lane] = ul;
    }
}

// ---------------- final MLP tail --------------------------------------------
__global__ void k_dot3(const float* __restrict__ A3, const float* __restrict__ c3) {
    int gt = blockIdx.x * blockDim.x + threadIdx.x;
    int n = gt >> 5;
    int lane = gt & 31;
    if (n >= NN) return;
    const float4* pm = (const float4*)(g_m2 + (size_t)n * DH);
    const float4* pw = (const float4*)A3;
    float acc = 0.f;
    #pragma unroll
    for (int i = 0; i < DH / 128; i++) {
        int k = i * 32 + lane;
        float4 m = pm[k], w = pw[k];
        acc += m.x * w.x + m.y * w.y + m.z * w.z + m.w * w.w;
    }
    #pragma unroll
    for (int o = 16; o; o >>= 1) acc += __shfl_xor_sync(0xffffffffu, acc, o);
    if (lane == 0) g_logit[n] = acc + c3[0];
}

__global__ void k_softmax(float* __restrict__ out) {
    __shared__ float sh[1024];
    int t = threadIdx.x;
    float m = -3.0e38f;
    for (int i = t; i < NN; i += 1024) m = fmaxf(m, g_logit[i]);
    sh[t] = m; __syncthreads();
    for (int s = 512; s; s >>= 1) { if (t < s) sh[t] = fmaxf(sh[t], sh[t + s]); __syncthreads(); }
    float gm = sh[0]; __syncthreads();
    float sum = 0.f;
    for (int i = t; i < NN; i += 1024) sum += expf(g_logit[i] - gm);
    sh[t] = sum; __syncthreads();
    for (int s = 512; s; s >>= 1) { if (t < s) sh[t] += sh[t + s]; __syncthreads(); }
    float gs = sh[0];
    for (int i = t; i < NN; i += 1024) out[i] = expf(g_logit[i] - gm) / gs;
}

// ---------------- host side -------------------------------------------------
static __nv_bfloat16 *s_ahi, *s_alo, *s_whi, *s_wlo;

static void run_gemm(int K, int M, float* Cout, const float* bias, int mode) {
    dim3 g(M / 128, (NN + 127) / 128);
    k_gemm_mma<<<g, 256, SMEM_GEMM>>>(s_ahi, s_alo, s_whi, s_wlo, Cout, NN, K, M,
                                      bias, mode, s_ahi, s_alo);
}

static void prep_w(const float* W, int K, int M, int rofs) {
    dim3 g(K / 64, M / 32);
    k_prep_w<<<g, 256>>>(W, s_whi, s_wlo, K, M, rofs);
}

static void gat_layer(int din, const float* Wl, const float* Wr,
                      const float* att, const float* bias, float* xlr) {
    prep_w(Wl, din, DE, 0);
    prep_w(Wr, din, DE, DE);
    run_gemm(din, 2 * DE, xlr, nullptr, 0);
    k_gat_edge<<<(NN * 32 + 255) / 256, 256>>>(att, bias);
}

extern "C" void kernel_launch(void* const* d_in, const int* in_sizes, int n_in,
                              void* d_out, int out_size) {
    const float* x   = (const float*)d_in[0];
    const int*   ei  = (const int*)d_in[1];
    const float* Wl1 = (const float*)d_in[2];
    const float* Wr1 = (const float*)d_in[3];
    const float* at1 = (const float*)d_in[4];
    const float* b1  = (const float*)d_in[5];
    const float* Wl2 = (const float*)d_in[6];
    const float* Wr2 = (const float*)d_in[7];
    const float* at2 = (const float*)d_in[8];
    const float* b2  = (const float*)d_in[9];
    const float* Wl3 = (const float*)d_in[10];
    const float* Wr3 = (const float*)d_in[11];
    const float* at3 = (const float*)d_in[12];
    const float* b3  = (const float*)d_in[13];
    const float* A1  = (const float*)d_in[14];
    const float* c1  = (const float*)d_in[15];
    const float* A2  = (const float*)d_in[16];
    const float* c2  = (const float*)d_in[17];
    const float* A3  = (const float*)d_in[18];
    const float* c3  = (const float*)d_in[19];
    float* out = (float*)d_out;

    cudaFuncSetAttribute(k_gemm_mma, cudaFuncAttributeMaxDynamicSharedMemorySize, SMEM_GEMM);

    float *xlr, *m1, *m2;
    cudaGetSymbolAddress((void**)&xlr, g_xlr);
    cudaGetSymbolAddress((void**)&m1,  g_m1);
    cudaGetSymbolAddress((void**)&m2,  g_m2);
    cudaGetSymbolAddress((void**)&s_ahi, g_ahi);
    cudaGetSymbolAddress((void**)&s_alo, g_alo);
    cudaGetSymbolAddress((void**)&s_whi, g_whi);
    cudaGetSymbolAddress((void**)&s_wlo, g_wlo);

    // edges + CSR by dst (4 launches)
    k_detect<<<1, 256>>>(ei);
    k_edges<<<(NE + 255) / 256, 256>>>(ei);
    k_scan<<<1, 1024>>>();
    k_scatter<<<(NE + 255) / 256, 256>>>();

    // layer 1 input split
    k_split<<<(NN * DI + 255) / 256, 256>>>(x, s_ahi, s_alo, NN * DI);

    gat_layer(DI, Wl1, Wr1, at1, b1, xlr);
    gat_layer(DE, Wl2, Wr2, at2, b2, xlr);
    gat_layer(DE, Wl3, Wr3, at3, b3, xlr);

    // MLP
    prep_w(A1, DE, DH, 0);
    run_gemm(DE, DH, m1, c1, 3);
    prep_w(A2, DH, DH, 0);
    run_gemm(DH, DH, m2, c2, 1);
    k_dot3<<<(NN * 32 + 255) / 256, 256>>>(A3, c3);
    k_softmax<<<1, 1024>>>(out);
}

// round 12
// speedup vs baseline: 2.2814x; 1.0028x over previous
#include <cuda_runtime.h>
#include <cuda_bf16.h>
#include <math.h>
#include <stdint.h>

#define NN 10000
#define NE 160000
#define DI 128
#define DE 512
#define DH 256

// ---------------- scratch (device globals; no allocation allowed) ----------
__device__ __align__(16) float g_xlr[NN * 2 * DE];   // [node][xl(512) | xr(512)]
__device__ int   g_src[NE];
__device__ int   g_dst[NE];
__device__ int   g_deg[NN];
__device__ int   g_rs[NN + 1];
__device__ int   g_cur[NN];
__device__ int   g_csrc[NE];
__device__ __align__(16) float g_m1[NN * DH];
__device__ __align__(16) float g_m2[NN * DH];
__device__ float g_logit[NN];
__device__ int   g_is64;
__device__ __align__(16) __nv_bfloat16 g_ahi[NN * DE];
__device__ __align__(16) __nv_bfloat16 g_alo[NN * DE];
__device__ __align__(16) __nv_bfloat16 g_bhi[NN * DH];   // MLP split output (race fix)
__device__ __align__(16) __nv_bfloat16 g_blo[NN * DH];
__device__ __align__(16) __nv_bfloat16 g_whi[2 * DE * DE];
__device__ __align__(16) __nv_bfloat16 g_wlo[2 * DE * DE];

// ---------------- edge decode (+ degree histogram fused) --------------------
__global__ void k_detect(const int* __restrict__ w) {
    __shared__ int s;
    if (threadIdx.x == 0) s = 0;
    __syncthreads();
    int acc = 0;
    for (int i = threadIdx.x; i < 2048; i += 256) acc |= w[2 * i + 1];
    atomicOr(&s, acc);
    for (int i = threadIdx.x; i < NN; i += 256) g_deg[i] = 0;
    __syncthreads();
    if (threadIdx.x == 0) g_is64 = (s == 0) ? 1 : 0;
}

__global__ void k_edges(const int* __restrict__ w) {
    int i = blockIdx.x * blockDim.x + threadIdx.x;
    if (i >= NE) return;
    int s, d;
    if (g_is64) { s = w[2 * i]; d = w[2 * (NE + i)]; }
    else        { s = w[i];     d = w[NE + i]; }
    if ((unsigned)s >= NN) s = 0;
    if ((unsigned)d >= NN) d = 0;
    g_src[i] = s;
    g_dst[i] = d;
    atomicAdd(&g_deg[d], 1);
}

// coalesced chunked scan: 10 chunks of 1024, warp-shuffle within chunk
__global__ void k_scan() {
    __shared__ int wsum[32];
    __shared__ int sbase;
    int t = threadIdx.x;
    int lane = t & 31, w = t >> 5;
    if (t == 0) sbase = 0;
    __syncthreads();
    for (int c = 0; c < NN; c += 1024) {
        int idx = c + t;
        int v = (idx < NN) ? g_deg[idx] : 0;
        int inc = v;
        #pragma unroll
        for (int o = 1; o < 32; o <<= 1) {
            int u = __shfl_up_sync(0xffffffffu, inc, o);
            if (lane >= o) inc += u;
        }
        if (lane == 31) wsum[w] = inc;
        __syncthreads();
        if (w == 0) {
            int vv = wsum[lane];
            #pragma unroll
            for (int o = 1; o < 32; o <<= 1) {
                int u = __shfl_up_sync(0xffffffffu, vv, o);
                if (lane >= o) vv += u;
            }
            wsum[lane] = vv;
        }
        __syncthreads();
        int base = sbase + ((w > 0) ? wsum[w - 1] : 0) + inc - v;
        if (idx < NN) { g_rs[idx] = base; g_cur[idx] = base; }
        __syncthreads();
        if (t == 0) sbase += wsum[31];
        __syncthreads();
    }
    if (t == 0) g_rs[NN] = sbase;
}

__global__ void k_scatter() {
    int i = blockIdx.x * blockDim.x + threadIdx.x;
    if (i >= NE) return;
    int pos = atomicAdd(&g_cur[g_dst[i]], 1);
    g_csrc[pos] = g_src[i];
}

// ---------------- hi/lo split (layer-1 input only) ---------------------------
__global__ void k_split(const float* __restrict__ a, __nv_bfloat16* __restrict__ hi,
                        __nv_bfloat16* __restrict__ lo, int n) {
    int i = blockIdx.x * blockDim.x + threadIdx.x;
    if (i >= n) return;
    float v = a[i];
    __nv_bfloat16 h = __float2bfloat16_rn(v);
    hi[i] = h;
    lo[i] = __float2bfloat16_rn(v - __bfloat162float(h));
}

// ---------------- coalesced weight prep: W[K,M] -> WT[m+rofs][K] hi/lo -------
__global__ __launch_bounds__(256) void k_prep_w(
    const float* __restrict__ W, __nv_bfloat16* __restrict__ hiT,
    __nv_bfloat16* __restrict__ loT, int K, int M, int rofs) {
    __shared__ float s[64][33];
    int k0 = blockIdx.x * 64, m0 = blockIdx.y * 32;
    int tid = threadIdx.x;
    #pragma unroll
    for (int i = tid; i < 64 * 32; i += 256) {
        int kk = i >> 5, mm = i & 31;
        s[kk][mm] = W[(size_t)(k0 + kk) * M + m0 + mm];
    }
    __syncthreads();
    #pragma unroll
    for (int i = tid; i < 32 * 32; i += 256) {
        int mm = i >> 5, kp = i & 31;
        float v0 = s[2 * kp][mm], v1 = s[2 * kp + 1][mm];
        __nv_bfloat162 h2 = __floats2bfloat162_rn(v0, v1);
        float l0 = v0 - __bfloat162float(__low2bfloat16(h2));
        float l1 = v1 - __bfloat162float(__high2bfloat16(h2));
        __nv_bfloat162 l2 = __floats2bfloat162_rn(l0, l1);
        size_t ro = (size_t)(m0 + mm + rofs) * K + k0 + 2 * kp;
        *(uint32_t*)(hiT + ro) = *(uint32_t*)&h2;
        *(uint32_t*)(loT + ro) = *(uint32_t*)&l2;
    }
}

// ---------------- cp.async + ldmatrix bf16 GEMM (3-pass hi/lo) --------------
#define TPAD 40
#define TILE_E (128 * TPAD)
#define STAGE_E (4 * TILE_E)
#define SMEM_GEMM (2 * STAGE_E * 2)

__device__ __forceinline__ void cpa16(uint32_t dst, const void* src, int sz) {
    asm volatile("cp.async.cg.shared.global [%0], [%1], 16, %2;"
                 :: "r"(dst), "l"(src), "r"(sz) : "memory");
}
__device__ __forceinline__ void cpa_commit() {
    asm volatile("cp.async.commit_group;" ::: "memory");
}
template<int N> __device__ __forceinline__ void cpa_wait() {
    asm volatile("cp.async.wait_group %0;" :: "n"(N) : "memory");
}
__device__ __forceinline__ void ldsm4(uint32_t* r, uint32_t addr) {
    asm volatile("ldmatrix.sync.aligned.m8n8.x4.shared.b16 {%0,%1,%2,%3}, [%4];"
                 : "=r"(r[0]), "=r"(r[1]), "=r"(r[2]), "=r"(r[3]) : "r"(addr));
}

// mode bit0: bias + leaky(0.1); mode bit1: also write bf16 hi/lo to Hi/Lo[r*M+c]
// NOTE: Hi/Lo must NOT alias Ahi/Alo (cross-CTA RAW race) — caller provides
// dedicated split buffers.
__global__ __launch_bounds__(256, 2) void k_gemm_mma(
    const __nv_bfloat16* __restrict__ Ahi, const __nv_bfloat16* __restrict__ Alo,
    const __nv_bfloat16* __restrict__ BhiT, const __nv_bfloat16* __restrict__ BloT,
    float* __restrict__ C, int Nrows, int K, int M,
    const float* __restrict__ bias, int mode,
    __nv_bfloat16* __restrict__ Hi, __nv_bfloat16* __restrict__ Lo)
{
    extern __shared__ __nv_bfloat16 smem[];
    uint32_t sb = (uint32_t)__cvta_generic_to_shared(smem);

    int tid = threadIdx.x;
    int wid = tid >> 5, lane = tid & 31;
    int wm = wid & 1, wn = wid >> 1;
    int row0 = blockIdx.y * 128;
    int col0 = blockIdx.x * 128;
    int mBase = wm * 64, nBase = wn * 32;
    int g = lane >> 2, cw = lane & 3;
    int mat = lane >> 3, r8 = lane & 7;
    int rsel = (mat & 1) * 8 + r8;
    int csel = (mat >> 1) * 8;

    float acc[4][4][4];
    #pragma unroll
    for (int a = 0; a < 4; a++)
        #pragma unroll
        for (int b = 0; b < 4; b++)
            #pragma unroll
            for (int c = 0; c < 4; c++) acc[a][b][c] = 0.f;

    int nk = K / 32;
    int c0 = tid * 2;

    auto prefetch = [&](int ck, int stage) {
        int kofs = ck * 32;
        uint32_t se = (uint32_t)stage * STAGE_E;
        #pragma unroll
        for (int i = 0; i < 2; i++) {
            int c = c0 + i;
            int r = c >> 2, seg = c & 3;
            uint32_t dA = sb + 2 * (se + r * TPAD + seg * 8);
            int gr = row0 + r;
            int szA = (gr < Nrows) ? 16 : 0;
            const __nv_bfloat16* pa = Ahi + (size_t)gr * K + kofs + seg * 8;
            const __nv_bfloat16* pl = Alo + (size_t)gr * K + kofs + seg * 8;
            if (szA == 0) { pa = Ahi; pl = Alo; }
            cpa16(dA, pa, szA);
            cpa16(dA + 2 * TILE_E, pl, szA);
            const __nv_bfloat16* pb = BhiT + (size_t)(col0 + r) * K + kofs + seg * 8;
            const __nv_bfloat16* pq = BloT + (size_t)(col0 + r) * K + kofs + seg * 8;
            cpa16(dA + 2 * (2 * TILE_E), pb, 16);
            cpa16(dA + 2 * (3 * TILE_E), pq, 16);
        }
        cpa_commit();
    };

    prefetch(0, 0);

    for (int ck = 0; ck < nk; ck++) {
        int stage = ck & 1;
        if (ck + 1 < nk) { prefetch(ck + 1, stage ^ 1); cpa_wait<1>(); }
        else             { cpa_wait<0>(); }
        __syncthreads();

        uint32_t se = (uint32_t)stage * STAGE_E;
        #pragma unroll
        for (int pass = 0; pass < 3; pass++) {
            uint32_t aoff = se + ((pass == 1) ? TILE_E : 0u);
            uint32_t boff = se + ((pass == 2) ? 3u * TILE_E : 2u * TILE_E);
            #pragma unroll
            for (int ks = 0; ks < 2; ks++) {
                int kw = ks * 16 + csel;
                uint32_t af[4][4];
                #pragma unroll
                for (int mi = 0; mi < 4; mi++)
                    ldsm4(af[mi], sb + 2 * (aoff + (uint32_t)(mBase + mi * 16 + rsel) * TPAD + kw));
                uint32_t bfr[2][4];
                #pragma unroll
                for (int p = 0; p < 2; p++)
                    ldsm4(bfr[p], sb + 2 * (boff + (uint32_t)(nBase + p * 16 + rsel) * TPAD + kw));
                #pragma unroll
                for (int mi = 0; mi < 4; mi++)
                    #pragma unroll
                    for (int ni = 0; ni < 4; ni++) {
                        float* d = acc[mi][ni];
                        uint32_t b0 = bfr[ni >> 1][ni & 1];
                        uint32_t b1 = bfr[ni >> 1][2 + (ni & 1)];
                        asm volatile(
                            "mma.sync.aligned.m16n8k16.row.col.f32.bf16.bf16.f32 "
                            "{%0,%1,%2,%3}, {%4,%5,%6,%7}, {%8,%9}, {%0,%1,%2,%3};"
                            : "+f"(d[0]), "+f"(d[1]), "+f"(d[2]), "+f"(d[3])
                            : "r"(af[mi][0]), "r"(af[mi][1]), "r"(af[mi][2]), "r"(af[mi][3]),
                              "r"(b0), "r"(b1));
                    }
            }
        }
        __syncthreads();
    }

    #pragma unroll
    for (int mi = 0; mi < 4; mi++) {
        int r0 = row0 + mBase + mi * 16 + g;
        #pragma unroll
        for (int ni = 0; ni < 4; ni++) {
            int cc = col0 + nBase + ni * 8 + cw * 2;
            float v0 = acc[mi][ni][0], v1 = acc[mi][ni][1];
            float v2 = acc[mi][ni][2], v3 = acc[mi][ni][3];
            if (mode & 1) {
                float b0 = bias[cc], b1 = bias[cc + 1];
                v0 += b0; v0 = (v0 > 0.f) ? v0 : 0.1f * v0;
                v1 += b1; v1 = (v1 > 0.f) ? v1 : 0.1f * v1;
                v2 += b0; v2 = (v2 > 0.f) ? v2 : 0.1f * v2;
                v3 += b1; v3 = (v3 > 0.f) ? v3 : 0.1f * v3;
            }
            if (r0 < Nrows) {
                *(float2*)(C + (size_t)r0 * M + cc) = make_float2(v0, v1);
                if (mode & 2) {
                    __nv_bfloat162 h2 = __floats2bfloat162_rn(v0, v1);
                    float l0 = v0 - __bfloat162float(__low2bfloat16(h2));
                    float l1 = v1 - __bfloat162float(__high2bfloat16(h2));
                    __nv_bfloat162 l2 = __floats2bfloat162_rn(l0, l1);
                    *(uint32_t*)(Hi + (size_t)r0 * M + cc) = *(uint32_t*)&h2;
                    *(uint32_t*)(Lo + (size_t)r0 * M + cc) = *(uint32_t*)&l2;
                }
            }
            if (r0 + 8 < Nrows) {
                *(float2*)(C + (size_t)(r0 + 8) * M + cc) = make_float2(v2, v3);
                if (mode & 2) {
                    __nv_bfloat162 h2 = __floats2bfloat162_rn(v2, v3);
                    float l0 = v2 - __bfloat162float(__low2bfloat16(h2));
                    float l1 = v3 - __bfloat162float(__high2bfloat16(h2));
                    __nv_bfloat162 l2 = __floats2bfloat162_rn(l0, l1);
                    *(uint32_t*)(Hi + (size_t)(r0 + 8) * M + cc) = *(uint32_t*)&h2;
                    *(uint32_t*)(Lo + (size_t)(r0 + 8) * M + cc) = *(uint32_t*)&l2;
                }
            }
        }
    }
}

// ---------------- fused GATv2 edge kernel: one-pass online softmax ----------
__global__ __launch_bounds__(256) void k_gat_edge(const float* __restrict__ att,
                                                  const float* __restrict__ bias) {
    int gw = (blockIdx.x * 256 + threadIdx.x) >> 5;
    int lane = threadIdx.x & 31;
    if (gw >= NN) return;
    int d = gw;
    int rs = g_rs[d], re = g_rs[d + 1];

    float4 xr4[4], at4[4];
    const float4* pxr = (const float4*)(g_xlr + (size_t)d * 1024 + 512);
    const float4* pat = (const float4*)att;
    #pragma unroll
    for (int j = 0; j < 4; j++) {
        xr4[j] = pxr[j * 32 + lane];
        at4[j] = pat[j * 32 + lane];
    }

    float m = -3.0e38f;
    float den = 0.f;
    float accf[16];
    #pragma unroll
    for (int j = 0; j < 16; j++) accf[j] = 0.f;

    for (int e = rs; e < re; e++) {
        int s = g_csrc[e];
        const float4* pxl = (const float4*)(g_xlr + (size_t)s * 1024);
        float4 a[4];
        float lg = 0.f;
        #pragma unroll
        for (int j = 0; j < 4; j++) {
            a[j] = pxl[j * 32 + lane];
            float v;
            v = a[j].x + xr4[j].x; v = v > 0.f ? v : 0.2f * v; lg += v * at4[j].x;
            v = a[j].y + xr4[j].y; v = v > 0.f ? v : 0.2f * v; lg += v * at4[j].y;
            v = a[j].z + xr4[j].z; v = v > 0.f ? v : 0.2f * v; lg += v * at4[j].z;
            v = a[j].w + xr4[j].w; v = v > 0.f ? v : 0.2f * v; lg += v * at4[j].w;
        }
        #pragma unroll
        for (int o = 16; o; o >>= 1) lg += __shfl_xor_sync(0xffffffffu, lg, o);

        if (lg > m) {
            float scale = expf(m - lg);
            den *= scale;
            #pragma unroll
            for (int j = 0; j < 16; j++) accf[j] *= scale;
            m = lg;
        }
        float w = expf(lg - m);
        den += w;
        #pragma unroll
        for (int j = 0; j < 4; j++) {
            accf[4 * j + 0] += w * a[j].x;
            accf[4 * j + 1] += w * a[j].y;
            accf[4 * j + 2] += w * a[j].z;
            accf[4 * j + 3] += w * a[j].w;
        }
    }

    float inv = 1.0f / (den + 1e-16f);
    const float4* pb = (const float4*)bias;
    __nv_bfloat16* ph = g_ahi + (size_t)d * DE;
    __nv_bfloat16* pl = g_alo + (size_t)d * DE;
    #pragma unroll
    for (int j = 0; j < 4; j++) {
        float4 b = pb[j * 32 + lane];
        float t0 = tanhf(accf[4 * j + 0] * inv + b.x);
        float t1 = tanhf(accf[4 * j + 1] * inv + b.y);
        float t2 = tanhf(accf[4 * j + 2] * inv + b.z);
        float t3 = tanhf(accf[4 * j + 3] * inv + b.w);
        __nv_bfloat162 h01 = __floats2bfloat162_rn(t0, t1);
        __nv_bfloat162 h23 = __floats2bfloat162_rn(t2, t3);
        float l0 = t0 - __bfloat162float(__low2bfloat16(h01));
        float l1 = t1 - __bfloat162float(__high2bfloat16(h01));
        float l2 = t2 - __bfloat162float(__low2bfloat16(h23));
        float l3 = t3 - __bfloat162float(__high2bfloat16(h23));
        __nv_bfloat162 q01 = __floats2bfloat162_rn(l0, l1);
        __nv_bfloat162 q23 = __floats2bfloat162_rn(l2, l3);
        uint2 uh, ul;
        uh.x = *(uint32_t*)&h01; uh.y = *(uint32_t*)&h23;
        ul.x = *(uint32_t*)&q01; ul.y = *(uint32_t*)&q23;
        ((uint2*)ph)[j * 32 + lane] = uh;
        ((uint2*)pl)[j * 32 + lane] = ul;
    }
}

// ---------------- final MLP tail --------------------------------------------
__global__ void k_dot3(const float* __restrict__ A3, const float* __restrict__ c3) {
    int gt = blockIdx.x * blockDim.x + threadIdx.x;
    int n = gt >> 5;
    int lane = gt & 31;
    if (n >= NN) return;
    const float4* pm = (const float4*)(g_m2 + (size_t)n * DH);
    const float4* pw = (const float4*)A3;
    float acc = 0.f;
    #pragma unroll
    for (int i = 0; i < DH / 128; i++) {
        int k = i * 32 + lane;
        float4 m = pm[k], w = pw[k];
        acc += m.x * w.x + m.y * w.y + m.z * w.z + m.w * w.w;
    }
    #pragma unroll
    for (int o = 16; o; o >>= 1) acc += __shfl_xor_sync(0xffffffffu, acc, o);
    if (lane == 0) g_logit[n] = acc + c3[0];
}

__global__ void k_softmax(float* __restrict__ out) {
    __shared__ float sh[1024];
    int t = threadIdx.x;
    float m = -3.0e38f;
    for (int i = t; i < NN; i += 1024) m = fmaxf(m, g_logit[i]);
    sh[t] = m; __syncthreads();
    for (int s = 512; s; s >>= 1) { if (t < s) sh[t] = fmaxf(sh[t], sh[t + s]); __syncthreads(); }
    float gm = sh[0]; __syncthreads();
    float sum = 0.f;
    for (int i = t; i < NN; i += 1024) sum += expf(g_logit[i] - gm);
    sh[t] = sum; __syncthreads();
    for (int s = 512; s; s >>= 1) { if (t < s) sh[t] += sh[t + s]; __syncthreads(); }
    float gs = sh[0];
    for (int i = t; i < NN; i += 1024) out[i] = expf(g_logit[i] - gm) / gs;
}

// ---------------- host side -------------------------------------------------
static __nv_bfloat16 *s_ahi, *s_alo, *s_bhi, *s_blo, *s_whi, *s_wlo;

static void run_gemm(const __nv_bfloat16* Ahi, const __nv_bfloat16* Alo,
                     int K, int M, float* Cout, const float* bias, int mode,
                     __nv_bfloat16* Hi, __nv_bfloat16* Lo) {
    dim3 g(M / 128, (NN + 127) / 128);
    k_gemm_mma<<<g, 256, SMEM_GEMM>>>(Ahi, Alo, s_whi, s_wlo, Cout, NN, K, M,
                                      bias, mode, Hi, Lo);
}

static void prep_w(const float* W, int K, int M, int rofs) {
    dim3 g(K / 64, M / 32);
    k_prep_w<<<g, 256>>>(W, s_whi, s_wlo, K, M, rofs);
}

static void gat_layer(int din, const float* Wl, const float* Wr,
                      const float* att, const float* bias, float* xlr) {
    prep_w(Wl, din, DE, 0);
    prep_w(Wr, din, DE, DE);
    run_gemm(s_ahi, s_alo, din, 2 * DE, xlr, nullptr, 0, nullptr, nullptr);
    k_gat_edge<<<(NN * 32 + 255) / 256, 256>>>(att, bias);
}

extern "C" void kernel_launch(void* const* d_in, const int* in_sizes, int n_in,
                              void* d_out, int out_size) {
    const float* x   = (const float*)d_in[0];
    const int*   ei  = (const int*)d_in[1];
    const float* Wl1 = (const float*)d_in[2];
    const float* Wr1 = (const float*)d_in[3];
    const float* at1 = (const float*)d_in[4];
    const float* b1  = (const float*)d_in[5];
    const float* Wl2 = (const float*)d_in[6];
    const float* Wr2 = (const float*)d_in[7];
    const float* at2 = (const float*)d_in[8];
    const float* b2  = (const float*)d_in[9];
    const float* Wl3 = (const float*)d_in[10];
    const float* Wr3 = (const float*)d_in[11];
    const float* at3 = (const float*)d_in[12];
    const float* b3  = (const float*)d_in[13];
    const float* A1  = (const float*)d_in[14];
    const float* c1  = (const float*)d_in[15];
    const float* A2  = (const float*)d_in[16];
    const float* c2  = (const float*)d_in[17];
    const float* A3  = (const float*)d_in[18];
    const float* c3  = (const float*)d_in[19];
    float* out = (float*)d_out;

    cudaFuncSetAttribute(k_gemm_mma, cudaFuncAttributeMaxDynamicSharedMemorySize, SMEM_GEMM);

    float *xlr, *m1, *m2;
    cudaGetSymbolAddress((void**)&xlr, g_xlr);
    cudaGetSymbolAddress((void**)&m1,  g_m1);
    cudaGetSymbolAddress((void**)&m2,  g_m2);
    cudaGetSymbolAddress((void**)&s_ahi, g_ahi);
    cudaGetSymbolAddress((void**)&s_alo, g_alo);
    cudaGetSymbolAddress((void**)&s_bhi, g_bhi);
    cudaGetSymbolAddress((void**)&s_blo, g_blo);
    cudaGetSymbolAddress((void**)&s_whi, g_whi);
    cudaGetSymbolAddress((void**)&s_wlo, g_wlo);

    // edges + CSR by dst (4 launches)
    k_detect<<<1, 256>>>(ei);
    k_edges<<<(NE + 255) / 256, 256>>>(ei);
    k_scan<<<1, 1024>>>();
    k_scatter<<<(NE + 255) / 256, 256>>>();

    // layer 1 input split
    k_split<<<(NN * DI + 255) / 256, 256>>>(x, s_ahi, s_alo, NN * DI);

    gat_layer(DI, Wl1, Wr1, at1, b1, xlr);
    gat_layer(DE, Wl2, Wr2, at2, b2, xlr);
    gat_layer(DE, Wl3, Wr3, at3, b3, xlr);

    // MLP: split epilogue writes to g_bhi/g_blo (must not alias the A operand)
    prep_w(A1, DE, DH, 0);
    run_gemm(s_ahi, s_alo, DE, DH, m1, c1, 3, s_bhi, s_blo);
    prep_w(A2, DH, DH, 0);
    run_gemm(s_bhi, s_blo, DH, DH, m2, c2, 1, nullptr, nullptr);
    k_dot3<<<(NN * 32 + 255) / 256, 256>>>(A3, c3);
    k_softmax<<<1, 1024>>>(out);
}